// round 6
// baseline (speedup 1.0000x reference)
#include <cuda_runtime.h>
#include <cuda_bf16.h>
#include <math.h>
#include <stdint.h>

// Problem constants
#define T_SEQ 4096
#define D_MODEL 2048
#define DH 128
#define NH 16
#define NKV 4
#define DKV 512   // NKV * DH
#define NQKV 3072 // D_MODEL + 2*DKV

// ---------------------------------------------------------------------------
// Scratch (device globals — no allocations allowed)
// ---------------------------------------------------------------------------
__device__ float g_Q[(size_t)NH * T_SEQ * DH];       // [h][t][d]   (roped, tf32)
__device__ float g_K[(size_t)NKV * DH * T_SEQ];      // [kh][d][t]  (roped, tf32)
__device__ float g_V[(size_t)T_SEQ * DKV];           // [t][kh*128+d] (tf32)
__device__ float g_C[(size_t)T_SEQ * D_MODEL];       // ctx [t][h*128+d] (tf32)
__device__ float g_Xr[(size_t)T_SEQ * D_MODEL];      // x rounded to tf32
__device__ float g_Wqkv[(size_t)NQKV * D_MODEL];     // [WQ^T;WK^T;WV^T] [n][k] tf32
__device__ float g_WOt[(size_t)D_MODEL * D_MODEL];   // WO^T [n][k] tf32

// ---------------------------------------------------------------------------
// Helpers (sm_80-compatible PTX only: mma.sync, cp.async, shfl)
// ---------------------------------------------------------------------------
__device__ __forceinline__ uint32_t smem_to_u32(const void* p) {
    uint32_t a;
    asm("{ .reg .u64 t; cvta.to.shared.u64 t, %1; cvt.u32.u64 %0, t; }"
        : "=r"(a) : "l"(p));
    return a;
}

__device__ __forceinline__ void cp_async16(uint32_t saddr, const void* g) {
    asm volatile("cp.async.cg.shared.global [%0], [%1], 16;" :: "r"(saddr), "l"(g));
}
#define CP_COMMIT() asm volatile("cp.async.commit_group;" ::: "memory")
#define CP_WAIT_0() asm volatile("cp.async.wait_group 0;" ::: "memory")
#define CP_WAIT_1() asm volatile("cp.async.wait_group 1;" ::: "memory")

__device__ __forceinline__ float to_tf32(float x) {
    uint32_t u;
    asm("cvt.rna.tf32.f32 %0, %1;" : "=r"(u) : "f"(x));
    return __uint_as_float(u);
}

// D += A(16x8, tf32 row) * B(8x8, tf32 col)  — fp32 accumulate
__device__ __forceinline__ void mma_tf32(float* d, const uint32_t* a, const uint32_t* b) {
    asm volatile(
        "mma.sync.aligned.m16n8k8.row.col.f32.tf32.tf32.f32 "
        "{%0,%1,%2,%3}, {%4,%5,%6,%7}, {%8,%9}, {%0,%1,%2,%3};"
        : "+f"(d[0]), "+f"(d[1]), "+f"(d[2]), "+f"(d[3])
        : "r"(a[0]), "r"(a[1]), "r"(a[2]), "r"(a[3]), "r"(b[0]), "r"(b[1]));
}

#define FU(x) __float_as_uint(x)

// ---------------------------------------------------------------------------
// GEMM (mma.sync tf32): C[M,N] = A[M,K] @ Bt[N,K]^T
//   128x128 tile, 256 thr, warp grid 2m x 4n (warp 64x32), K-tile 32,
//   3-stage cp.async pipeline.
//   cmode 0: row-major C (O-projection).
//   cmode 3: fused QKV epilogue with RoPE:
//     n in [0,2048):     Q head-block [h][t][d], rope+tf32
//     n in [2048,2560):  K d-major [kh][d][t],   rope+tf32
//     n in [2560,3072):  V row-major [t][512],   tf32
// ---------------------------------------------------------------------------
#define GM_KT 32
#define GM_PAD 36
#define GM_STG 3
#define GM_SMEM (GM_STG * 128 * GM_PAD * 2 * 4)   // 110,592 B

__device__ __forceinline__ void gm_load_stage(
    const float* __restrict__ A, const float* __restrict__ Bt,
    uint32_t sA, uint32_t sB, int kt, int K, int tid)
{
    #pragma unroll
    for (int it = 0; it < 4; it++) {
        int idx = it * 256 + tid;
        int row = idx >> 3;
        int c   = idx & 7;
        uint32_t off = (uint32_t)(row * GM_PAD + c * 4) * 4;
        cp_async16(sA + off, A  + (size_t)row * K + kt * GM_KT + c * 4);
        cp_async16(sB + off, Bt + (size_t)row * K + kt * GM_KT + c * 4);
    }
}

__global__ __launch_bounds__(256)
void gemm_mma(const float* __restrict__ A, const float* __restrict__ Bt,
              float* __restrict__ C, int M, int N, int K, int cmode)
{
    extern __shared__ __align__(16) float gsm[];
    float* As = gsm;                           // [3][128][GM_PAD]
    float* Bs = gsm + GM_STG * 128 * GM_PAD;   // [3][128][GM_PAD]

    const int tid  = threadIdx.x;
    const int w    = tid >> 5;
    const int lane = tid & 31;
    const int g    = lane >> 2;
    const int qd   = lane & 3;
    const int wm   = w & 1;
    const int wn   = w >> 1;
    const int m0   = blockIdx.y * 128;
    const int n0   = blockIdx.x * 128;
    const int NKT  = K / GM_KT;

    const float* Ab = A  + (size_t)m0 * K;
    const float* Bb = Bt + (size_t)n0 * K;
    const uint32_t sAu = smem_to_u32(As);
    const uint32_t sBu = smem_to_u32(Bs);
    const uint32_t stg_f = 128 * GM_PAD;
    const uint32_t stg_b = stg_f * 4;

    float acc[4][4][4];
    #pragma unroll
    for (int mt = 0; mt < 4; mt++)
        #pragma unroll
        for (int nt = 0; nt < 4; nt++)
            #pragma unroll
            for (int e = 0; e < 4; e++) acc[mt][nt][e] = 0.f;

    gm_load_stage(Ab, Bb, sAu, sBu, 0, K, tid); CP_COMMIT();
    gm_load_stage(Ab, Bb, sAu + stg_b, sBu + stg_b, 1, K, tid); CP_COMMIT();

    for (int kt = 0; kt < NKT; kt++) {
        CP_WAIT_1();
        __syncthreads();
        if (kt + 2 < NKT) {
            int s2 = (kt + 2) % GM_STG;
            gm_load_stage(Ab, Bb, sAu + s2 * stg_b, sBu + s2 * stg_b, kt + 2, K, tid);
            CP_COMMIT();
        }
        const float* Ac = As + (kt % GM_STG) * stg_f;
        const float* Bc = Bs + (kt % GM_STG) * stg_f;

        #pragma unroll
        for (int kk = 0; kk < GM_KT; kk += 8) {
            uint32_t a[4][4];
            #pragma unroll
            for (int mt = 0; mt < 4; mt++) {
                int r = 64 * wm + 16 * mt + g;
                a[mt][0] = FU(Ac[(r    ) * GM_PAD + kk + qd    ]);
                a[mt][1] = FU(Ac[(r + 8) * GM_PAD + kk + qd    ]);
                a[mt][2] = FU(Ac[(r    ) * GM_PAD + kk + qd + 4]);
                a[mt][3] = FU(Ac[(r + 8) * GM_PAD + kk + qd + 4]);
            }
            uint32_t b[4][2];
            #pragma unroll
            for (int nt = 0; nt < 4; nt++) {
                int n = 32 * wn + 8 * nt + g;
                b[nt][0] = FU(Bc[n * GM_PAD + kk + qd    ]);
                b[nt][1] = FU(Bc[n * GM_PAD + kk + qd + 4]);
            }
            #pragma unroll
            for (int mt = 0; mt < 4; mt++)
                #pragma unroll
                for (int nt = 0; nt < 4; nt++)
                    mma_tf32(acc[mt][nt], a[mt], b[nt]);
        }
    }

    // epilogue
    #pragma unroll
    for (int mt = 0; mt < 4; mt++) {
        #pragma unroll
        for (int nt = 0; nt < 4; nt++) {
            int r = m0 + 64 * wm + 16 * mt + g;
            int c = n0 + 32 * wn + 8 * nt + 2 * qd;
            if (cmode == 0) {
                #pragma unroll
                for (int hf = 0; hf < 2; hf++) {
                    int rr = r + hf * 8;
                    *(float2*)&C[(size_t)rr * N + c] =
                        make_float2(acc[mt][nt][2*hf], acc[mt][nt][2*hf+1]);
                }
            } else if (c < D_MODEL) {
                // Q with RoPE -> g_Q[h][t][d]
                int i = (c & 127) >> 1;
                float omega = (float)(1.0 / pow(10000.0, (double)(2 * i) / (double)DH));
                #pragma unroll
                for (int hf = 0; hf < 2; hf++) {
                    int rr = r + hf * 8;
                    float s, co;
                    sincosf((float)rr * omega, &s, &co);
                    float v0 = acc[mt][nt][2*hf], v1 = acc[mt][nt][2*hf+1];
                    size_t base = ((size_t)(c >> 7) * T_SEQ + rr) * 128 + (c & 127);
                    *(float2*)&g_Q[base] =
                        make_float2(to_tf32(v0 * co - v1 * s), to_tf32(v0 * s + v1 * co));
                }
            } else if (c < D_MODEL + DKV) {
                // K with RoPE -> g_K[kh][d][t] (d-major)
                int d  = c - D_MODEL;
                int kh = d >> 7;
                int dd = d & 127;
                int i  = dd >> 1;
                float omega = (float)(1.0 / pow(10000.0, (double)(2 * i) / (double)DH));
                #pragma unroll
                for (int hf = 0; hf < 2; hf++) {
                    int rr = r + hf * 8;
                    float s, co;
                    sincosf((float)rr * omega, &s, &co);
                    float v0 = acc[mt][nt][2*hf], v1 = acc[mt][nt][2*hf+1];
                    size_t base = ((size_t)kh * DH + dd) * T_SEQ + rr;
                    g_K[base]         = to_tf32(v0 * co - v1 * s);
                    g_K[base + T_SEQ] = to_tf32(v0 * s + v1 * co);
                }
            } else {
                // V -> g_V[t][512], tf32-rounded
                int d = c - (D_MODEL + DKV);
                #pragma unroll
                for (int hf = 0; hf < 2; hf++) {
                    int rr = r + hf * 8;
                    *(float2*)&g_V[(size_t)rr * DKV + d] =
                        make_float2(to_tf32(acc[mt][nt][2*hf]), to_tf32(acc[mt][nt][2*hf+1]));
                }
            }
        }
    }
}

// ---------------------------------------------------------------------------
// Batched weight transpose + tf32 rounding: one launch for WQ/WK/WV/WO.
// z=0: WQ -> g_Wqkv rows [0,2048);  z=1: WK -> rows [2048,2560);
// z=2: WV -> rows [2560,3072);      z=3: WO -> g_WOt.
// ---------------------------------------------------------------------------
__global__ void transpose_rnd4(const float* __restrict__ WQ, const float* __restrict__ WK,
                               const float* __restrict__ WV, const float* __restrict__ WO)
{
    __shared__ float t[32][33];
    int z = blockIdx.z;
    const float* src;
    float* dst;
    int N;
    if (z == 0)      { src = WQ; dst = g_Wqkv;                              N = D_MODEL; }
    else if (z == 1) { src = WK; dst = g_Wqkv + (size_t)D_MODEL * D_MODEL;  N = DKV; }
    else if (z == 2) { src = WV; dst = g_Wqkv + (size_t)(D_MODEL + DKV) * D_MODEL; N = DKV; }
    else             { src = WO; dst = g_WOt;                               N = D_MODEL; }

    int n0 = blockIdx.x * 32;
    if (n0 >= N) return;
    int k0 = blockIdx.y * 32;
    #pragma unroll
    for (int i = threadIdx.y; i < 32; i += 8)
        t[i][threadIdx.x] = src[(size_t)(k0 + i) * N + n0 + threadIdx.x];
    __syncthreads();
    #pragma unroll
    for (int i = threadIdx.y; i < 32; i += 8)
        dst[(size_t)(n0 + i) * D_MODEL + k0 + threadIdx.x] = to_tf32(t[threadIdx.x][i]);
}

__global__ void round_tf32_kernel(const float4* __restrict__ in, float4* __restrict__ out, int n4)
{
    int i = blockIdx.x * blockDim.x + threadIdx.x;
    if (i < n4) {
        float4 v = in[i];
        v.x = to_tf32(v.x); v.y = to_tf32(v.y);
        v.z = to_tf32(v.z); v.w = to_tf32(v.w);
        out[i] = v;
    }
}

// ---------------------------------------------------------------------------
// Flash attention on mma.sync tf32. q-tile 128, kv-tile 64, 256 thr (8 warps).
// Warp w owns rows 16w..16w+15 -> softmax warp-local (quad shfl).
// Q fragments cached in registers (loaded once); the Qs smem region is then
// reused as the second V buffer. K and V double-buffered, prefetched one full
// kv-tile ahead; ONE __syncthreads per kv-tile.
// ---------------------------------------------------------------------------
#define QPAD 132
#define KPAD 72
#define VPAD 136
#define PPAD 68
#define FL_SMEM ((128*QPAD + 2*128*KPAD + 64*VPAD + 128*PPAD) * 4)  // 210,944 B

__global__ __launch_bounds__(256, 1)
void flash_mma(const float* __restrict__ Qg, const float* __restrict__ Kd,
               const float* __restrict__ Vt, float* __restrict__ Ctx)
{
    extern __shared__ __align__(16) float sm[];
    float* Qs  = sm;                        // [128][QPAD] -> later V buffer 1
    float* Ks  = Qs + 128 * QPAD;           // [2][128][KPAD]
    float* Vs0 = Ks + 2 * 128 * KPAD;       // [64][VPAD]  (V buffer 0)
    float* Ps  = Vs0 + 64 * VPAD;           // [128][PPAD]

    const int tid  = threadIdx.x;
    const int w    = tid >> 5;
    const int lane = tid & 31;
    const int g    = lane >> 2;
    const int qd   = lane & 3;
    const int qt   = gridDim.x - 1 - blockIdx.x;   // big tiles first
    const int h    = blockIdx.y;
    const int kh   = h >> 2;
    const int qbase = qt * 128;
    const int r0   = 16 * w + g;

    const float* Qh = Qg + (size_t)h * T_SEQ * DH;
    const float* Kh = Kd + (size_t)kh * DH * T_SEQ;
    const uint32_t ksu = smem_to_u32(Ks);
    const uint32_t v0u = smem_to_u32(Vs0);
    const uint32_t v1u = smem_to_u32(Qs);   // V buffer 1 aliases Qs

    const int ntiles = 2 * qt + 2;

    // prologue: issue K(0) and V(0) first (latency overlap with Q staging)
    #pragma unroll
    for (int it = 0; it < 8; it++) {
        int idx = it * 256 + tid;
        int d = idx >> 4, c = idx & 15;
        cp_async16(ksu + (uint32_t)(d * KPAD + c * 4) * 4,
                   Kh + (size_t)d * T_SEQ + c * 4);
    }
    CP_COMMIT();
    #pragma unroll
    for (int it = 0; it < 8; it++) {
        int idx = it * 256 + tid;
        int r = idx >> 5, c = idx & 31;
        cp_async16(v0u + (uint32_t)(r * VPAD + c * 4) * 4,
                   Vt + (size_t)r * DKV + kh * DH + c * 4);
    }
    CP_COMMIT();

    // stage Q tile in smem, then preload fragments into registers
    #pragma unroll
    for (int it = 0; it < 16; it++) {
        int idx = it * 256 + tid;
        int r = idx >> 5, c = (idx & 31) << 2;
        *(float4*)&Qs[r * QPAD + c] = *(const float4*)&Qh[(size_t)(qbase + r) * DH + c];
    }
    __syncthreads();

    uint32_t qf[16][4];
    #pragma unroll
    for (int kk = 0; kk < 16; kk++) {
        qf[kk][0] = FU(Qs[(r0    ) * QPAD + 8 * kk + qd    ]);
        qf[kk][1] = FU(Qs[(r0 + 8) * QPAD + 8 * kk + qd    ]);
        qf[kk][2] = FU(Qs[(r0    ) * QPAD + 8 * kk + qd + 4]);
        qf[kk][3] = FU(Qs[(r0 + 8) * QPAD + 8 * kk + qd + 4]);
    }

    float m_i[2] = {-1e30f, -1e30f};
    float l_i[2] = {0.f, 0.f};
    float o[16][4];
    #pragma unroll
    for (int nt = 0; nt < 16; nt++)
        #pragma unroll
        for (int e = 0; e < 4; e++) o[nt][e] = 0.f;

    const float SCALE = 0.08838834764831843f;   // 1/sqrt(128)

    for (int jt = 0; jt < ntiles; jt++) {
        CP_WAIT_0();        // K(jt), V(jt) landed
        __syncthreads();    // visible; jt-1 buffers fully consumed by all warps

        // prefetch K(jt+1), V(jt+1) into the other buffers
        if (jt + 1 < ntiles) {
            const int kb2 = (jt + 1) * 64;
            uint32_t kdst = ksu + (uint32_t)(((jt + 1) & 1) * 128 * KPAD) * 4;
            #pragma unroll
            for (int it = 0; it < 8; it++) {
                int idx = it * 256 + tid;
                int d = idx >> 4, c = idx & 15;
                cp_async16(kdst + (uint32_t)(d * KPAD + c * 4) * 4,
                           Kh + (size_t)d * T_SEQ + kb2 + c * 4);
            }
            CP_COMMIT();
            uint32_t vdst = ((jt + 1) & 1) ? v1u : v0u;
            #pragma unroll
            for (int it = 0; it < 8; it++) {
                int idx = it * 256 + tid;
                int r = idx >> 5, c = idx & 31;
                cp_async16(vdst + (uint32_t)(r * VPAD + c * 4) * 4,
                           Vt + (size_t)(kb2 + r) * DKV + kh * DH + c * 4);
            }
            CP_COMMIT();
        }

        const int kbase = jt * 64;
        const float* Kc = Ks + (jt & 1) * 128 * KPAD;
        const float* Vc = (jt & 1) ? Qs : Vs0;

        // S = Q @ K^T
        float s[8][4];
        #pragma unroll
        for (int nt = 0; nt < 8; nt++)
            #pragma unroll
            for (int e = 0; e < 4; e++) s[nt][e] = 0.f;

        #pragma unroll
        for (int kk = 0; kk < 16; kk++) {
            #pragma unroll
            for (int nt = 0; nt < 8; nt++) {
                uint32_t b[2];
                b[0] = FU(Kc[(8 * kk + qd    ) * KPAD + nt * 8 + g]);
                b[1] = FU(Kc[(8 * kk + qd + 4) * KPAD + nt * 8 + g]);
                mma_tf32(s[nt], qf[kk], b);
            }
        }

        #pragma unroll
        for (int nt = 0; nt < 8; nt++)
            #pragma unroll
            for (int e = 0; e < 4; e++) s[nt][e] *= SCALE;

        if (jt >= 2 * qt) {   // diagonal region: mask col > row
            #pragma unroll
            for (int nt = 0; nt < 8; nt++)
                #pragma unroll
                for (int e = 0; e < 4; e++) {
                    int col = kbase + nt * 8 + 2 * qd + (e & 1);
                    int row = qbase + r0 + ((e >> 1) << 3);
                    if (col > row) s[nt][e] = -1e30f;
                }
        }

        // online softmax (rows r0: e0,e1; r0+8: e2,e3) — quad shfl reduce
        float mx0 = -1e30f, mx1 = -1e30f;
        #pragma unroll
        for (int nt = 0; nt < 8; nt++) {
            mx0 = fmaxf(mx0, fmaxf(s[nt][0], s[nt][1]));
            mx1 = fmaxf(mx1, fmaxf(s[nt][2], s[nt][3]));
        }
        mx0 = fmaxf(mx0, __shfl_xor_sync(0xffffffffu, mx0, 1));
        mx0 = fmaxf(mx0, __shfl_xor_sync(0xffffffffu, mx0, 2));
        mx1 = fmaxf(mx1, __shfl_xor_sync(0xffffffffu, mx1, 1));
        mx1 = fmaxf(mx1, __shfl_xor_sync(0xffffffffu, mx1, 2));
        float mn0 = fmaxf(m_i[0], mx0);
        float mn1 = fmaxf(m_i[1], mx1);
        float sc0 = __expf(m_i[0] - mn0);
        float sc1 = __expf(m_i[1] - mn1);
        m_i[0] = mn0; m_i[1] = mn1;

        float rs0 = 0.f, rs1 = 0.f;
        #pragma unroll
        for (int nt = 0; nt < 8; nt++) {
            s[nt][0] = __expf(s[nt][0] - mn0);
            s[nt][1] = __expf(s[nt][1] - mn0);
            s[nt][2] = __expf(s[nt][2] - mn1);
            s[nt][3] = __expf(s[nt][3] - mn1);
            rs0 += s[nt][0] + s[nt][1];
            rs1 += s[nt][2] + s[nt][3];
        }
        rs0 += __shfl_xor_sync(0xffffffffu, rs0, 1);
        rs0 += __shfl_xor_sync(0xffffffffu, rs0, 2);
        rs1 += __shfl_xor_sync(0xffffffffu, rs1, 1);
        rs1 += __shfl_xor_sync(0xffffffffu, rs1, 2);
        l_i[0] = l_i[0] * sc0 + rs0;
        l_i[1] = l_i[1] * sc1 + rs1;

        #pragma unroll
        for (int nt = 0; nt < 16; nt++) {
            o[nt][0] *= sc0; o[nt][1] *= sc0;
            o[nt][2] *= sc1; o[nt][3] *= sc1;
        }
        // stage P (rounded) — warp-private rows, syncwarp suffices
        #pragma unroll
        for (int nt = 0; nt < 8; nt++) {
            *(float2*)&Ps[(r0    ) * PPAD + nt * 8 + 2 * qd] =
                make_float2(to_tf32(s[nt][0]), to_tf32(s[nt][1]));
            *(float2*)&Ps[(r0 + 8) * PPAD + nt * 8 + 2 * qd] =
                make_float2(to_tf32(s[nt][2]), to_tf32(s[nt][3]));
        }
        __syncwarp();

        // O += P @ V   (V already resident — prefetched last iteration)
        #pragma unroll
        for (int kk = 0; kk < 8; kk++) {
            uint32_t a[4];
            a[0] = FU(Ps[(r0    ) * PPAD + 8 * kk + qd    ]);
            a[1] = FU(Ps[(r0 + 8) * PPAD + 8 * kk + qd    ]);
            a[2] = FU(Ps[(r0    ) * PPAD + 8 * kk + qd + 4]);
            a[3] = FU(Ps[(r0 + 8) * PPAD + 8 * kk + qd + 4]);
            #pragma unroll
            for (int nt = 0; nt < 16; nt++) {
                uint32_t b[2];
                b[0] = FU(Vc[(8 * kk + qd    ) * VPAD + nt * 8 + g]);
                b[1] = FU(Vc[(8 * kk + qd + 4) * VPAD + nt * 8 + g]);
                mma_tf32(o[nt], a, b);
            }
        }
    }

    // epilogue: normalize, round to tf32 (feeds O-projection), write ctx
    float inv0 = 1.0f / l_i[0];
    float inv1 = 1.0f / l_i[1];
    #pragma unroll
    for (int nt = 0; nt < 16; nt++) {
        size_t b0 = (size_t)(qbase + r0    ) * D_MODEL + h * DH + nt * 8 + 2 * qd;
        size_t b1 = (size_t)(qbase + r0 + 8) * D_MODEL + h * DH + nt * 8 + 2 * qd;
        *(float2*)&Ctx[b0] = make_float2(to_tf32(o[nt][0] * inv0), to_tf32(o[nt][1] * inv0));
        *(float2*)&Ctx[b1] = make_float2(to_tf32(o[nt][2] * inv1), to_tf32(o[nt][3] * inv1));
    }
}

// ---------------------------------------------------------------------------
// kernel_launch
// ---------------------------------------------------------------------------
extern "C" void kernel_launch(void* const* d_in, const int* in_sizes, int n_in,
                              void* d_out, int out_size)
{
    const float* x  = (const float*)d_in[0];
    const float* WQ = (const float*)d_in[1];
    const float* WK = (const float*)d_in[2];
    const float* WV = (const float*)d_in[3];
    const float* WO = (const float*)d_in[4];
    float* out = (float*)d_out;

    float *qp, *kp, *vp, *cp, *xr, *wqkv, *wot;
    cudaGetSymbolAddress((void**)&qp,   g_Q);
    cudaGetSymbolAddress((void**)&kp,   g_K);
    cudaGetSymbolAddress((void**)&vp,   g_V);
    cudaGetSymbolAddress((void**)&cp,   g_C);
    cudaGetSymbolAddress((void**)&xr,   g_Xr);
    cudaGetSymbolAddress((void**)&wqkv, g_Wqkv);
    cudaGetSymbolAddress((void**)&wot,  g_WOt);

    cudaFuncSetAttribute(flash_mma,
                         cudaFuncAttributeMaxDynamicSharedMemorySize, FL_SMEM);
    cudaFuncSetAttribute(gemm_mma,
                         cudaFuncAttributeMaxDynamicSharedMemorySize, GM_SMEM);

    // 1) round x to tf32 (RNA)
    {
        int n4 = T_SEQ * D_MODEL / 4;
        round_tf32_kernel<<<(n4 + 255) / 256, 256>>>((const float4*)x, (float4*)xr, n4);
    }
    // 2) all weight transposes in one launch
    transpose_rnd4<<<dim3(64, 64, 4), dim3(32, 8)>>>(WQ, WK, WV, WO);

    // 3) fused QKV projection (epilogue applies RoPE + layouts)
    gemm_mma<<<dim3(NQKV/128, T_SEQ/128), 256, GM_SMEM>>>(xr, wqkv, nullptr,
                                                          T_SEQ, NQKV, D_MODEL, 3);

    // 4) attention (tensor cores; writes tf32-rounded ctx)
    flash_mma<<<dim3(T_SEQ/128, NH), 256, FL_SMEM>>>(qp, kp, vp, cp);

    // 5) output projection
    gemm_mma<<<dim3(D_MODEL/128, T_SEQ/128), 256, GM_SMEM>>>(cp, wot, out,
                                                             T_SEQ, D_MODEL, D_MODEL, 0);
}

// round 7
// speedup vs baseline: 1.0606x; 1.0606x over previous
#include <cuda_runtime.h>
#include <cuda_bf16.h>
#include <math.h>
#include <stdint.h>

// Problem constants
#define T_SEQ 4096
#define D_MODEL 2048
#define DH 128
#define NH 16
#define NKV 4
#define DKV 512   // NKV * DH
#define NQKV 3072 // D_MODEL + 2*DKV

// ---------------------------------------------------------------------------
// Scratch (device globals — no allocations allowed)
// ---------------------------------------------------------------------------
__device__ float g_Q[(size_t)NH * T_SEQ * DH];       // [h][t][d]   (roped, tf32)
__device__ float g_K[(size_t)NKV * T_SEQ * DH];      // [kh][t][d]  (roped, tf32)
__device__ float g_V[(size_t)NKV * DH * T_SEQ];      // [kh][d][t]  (tf32)
__device__ float g_C[(size_t)T_SEQ * D_MODEL];       // ctx [t][h*128+d] (tf32)
__device__ float g_Xr[(size_t)T_SEQ * D_MODEL];      // x rounded to tf32
__device__ float g_Wqkv[(size_t)NQKV * D_MODEL];     // [WQ^T;WK^T;WV^T] [n][k] tf32
__device__ float g_WOt[(size_t)D_MODEL * D_MODEL];   // WO^T [n][k] tf32

// ---------------------------------------------------------------------------
// Helpers (sm_80-era PTX only: mma.sync, ldmatrix, cp.async, shfl)
// ---------------------------------------------------------------------------
__device__ __forceinline__ uint32_t smem_to_u32(const void* p) {
    uint32_t a;
    asm("{ .reg .u64 t; cvta.to.shared.u64 t, %1; cvt.u32.u64 %0, t; }"
        : "=r"(a) : "l"(p));
    return a;
}

__device__ __forceinline__ void cp_async16(uint32_t saddr, const void* g) {
    asm volatile("cp.async.cg.shared.global [%0], [%1], 16;" :: "r"(saddr), "l"(g));
}
#define CP_COMMIT() asm volatile("cp.async.commit_group;" ::: "memory")
#define CP_WAIT_0() asm volatile("cp.async.wait_group 0;" ::: "memory")
#define CP_WAIT_1() asm volatile("cp.async.wait_group 1;" ::: "memory")

__device__ __forceinline__ float to_tf32(float x) {
    uint32_t u;
    asm("cvt.rna.tf32.f32 %0, %1;" : "=r"(u) : "f"(x));
    return __uint_as_float(u);
}

// D += A(16x8 tf32 row) * B(8x8 tf32 col) — fp32 accumulate
__device__ __forceinline__ void mma_tf32(float* d, const uint32_t* a, const uint32_t* b) {
    asm volatile(
        "mma.sync.aligned.m16n8k8.row.col.f32.tf32.tf32.f32 "
        "{%0,%1,%2,%3}, {%4,%5,%6,%7}, {%8,%9}, {%0,%1,%2,%3};"
        : "+f"(d[0]), "+f"(d[1]), "+f"(d[2]), "+f"(d[3])
        : "r"(a[0]), "r"(a[1]), "r"(a[2]), "r"(a[3]), "r"(b[0]), "r"(b[1]));
}

__device__ __forceinline__ void ldsm_x4(uint32_t& r0, uint32_t& r1,
                                        uint32_t& r2, uint32_t& r3, uint32_t addr) {
    asm volatile("ldmatrix.sync.aligned.m8n8.x4.shared.b16 {%0,%1,%2,%3}, [%4];"
                 : "=r"(r0), "=r"(r1), "=r"(r2), "=r"(r3) : "r"(addr));
}

#define FU(x) __float_as_uint(x)

// ---------------------------------------------------------------------------
// GEMM (mma.sync tf32 + ldmatrix): C[M,N] = A[M,K] @ Bt[N,K]^T
//   128x128 tile, 256 thr, warp grid 2m x 4n (warp 64x32), K-tile 32,
//   3-stage cp.async pipeline, 2 CTAs/SM.
//   cmode 0: row-major C (O-projection).  cmode 3: fused QKV epilogue + RoPE.
// ---------------------------------------------------------------------------
#define GM_KT 32
#define GM_PAD 36
#define GM_STG 3
#define GM_SMEM (GM_STG * 128 * GM_PAD * 2 * 4)   // 110,592 B

__device__ __forceinline__ void gm_load_stage(
    const float* __restrict__ A, const float* __restrict__ Bt,
    uint32_t sA, uint32_t sB, int kt, int K, int tid)
{
    #pragma unroll
    for (int it = 0; it < 4; it++) {
        int idx = it * 256 + tid;
        int row = idx >> 3;
        int c   = idx & 7;
        uint32_t off = (uint32_t)(row * GM_PAD + c * 4) * 4;
        cp_async16(sA + off, A  + (size_t)row * K + kt * GM_KT + c * 4);
        cp_async16(sB + off, Bt + (size_t)row * K + kt * GM_KT + c * 4);
    }
}

__global__ __launch_bounds__(256, 2)
void gemm_mma(const float* __restrict__ A, const float* __restrict__ Bt,
              float* __restrict__ C, int M, int N, int K, int cmode)
{
    extern __shared__ __align__(16) float gsm[];
    float* As = gsm;                           // [3][128][GM_PAD]
    float* Bs = gsm + GM_STG * 128 * GM_PAD;   // [3][128][GM_PAD]

    const int tid  = threadIdx.x;
    const int w    = tid >> 5;
    const int lane = tid & 31;
    const int g    = lane >> 2;
    const int qd   = lane & 3;
    const int lm   = lane >> 3;   // ldmatrix: matrix index
    const int lr   = lane & 7;    // ldmatrix: row within matrix
    const int wm   = w & 1;
    const int wn   = w >> 1;
    const int m0   = blockIdx.y * 128;
    const int n0   = blockIdx.x * 128;
    const int NKT  = K / GM_KT;

    const float* Ab = A  + (size_t)m0 * K;
    const float* Bb = Bt + (size_t)n0 * K;
    const uint32_t sAu = smem_to_u32(As);
    const uint32_t sBu = smem_to_u32(Bs);
    const uint32_t stg_b = 128 * GM_PAD * 4;

    // per-lane ldmatrix offsets (floats*4 = bytes)
    const uint32_t aOffL = (uint32_t)((((lm & 1) * 8 + lr) + 64 * wm + 0) * GM_PAD
                                      + (lm >> 1) * 4) * 4;
    const uint32_t bOffL = (uint32_t)((((lm >> 1) * 8 + lr) + 32 * wn) * GM_PAD
                                      + (lm & 1) * 4) * 4;

    float acc[4][4][4];
    #pragma unroll
    for (int mt = 0; mt < 4; mt++)
        #pragma unroll
        for (int nt = 0; nt < 4; nt++)
            #pragma unroll
            for (int e = 0; e < 4; e++) acc[mt][nt][e] = 0.f;

    gm_load_stage(Ab, Bb, sAu, sBu, 0, K, tid); CP_COMMIT();
    gm_load_stage(Ab, Bb, sAu + stg_b, sBu + stg_b, 1, K, tid); CP_COMMIT();

    for (int kt = 0; kt < NKT; kt++) {
        CP_WAIT_1();
        __syncthreads();
        if (kt + 2 < NKT) {
            int s2 = (kt + 2) % GM_STG;
            gm_load_stage(Ab, Bb, sAu + s2 * stg_b, sBu + s2 * stg_b, kt + 2, K, tid);
            CP_COMMIT();
        }
        uint32_t sa = sAu + (kt % GM_STG) * stg_b + aOffL;
        uint32_t sb = sBu + (kt % GM_STG) * stg_b + bOffL;

        #pragma unroll
        for (int kk = 0; kk < GM_KT; kk += 8) {
            uint32_t a[4][4];
            #pragma unroll
            for (int mt = 0; mt < 4; mt++)
                ldsm_x4(a[mt][0], a[mt][1], a[mt][2], a[mt][3],
                        sa + (uint32_t)(16 * mt * GM_PAD + kk) * 4);
            uint32_t b[4][2];
            #pragma unroll
            for (int ntp = 0; ntp < 2; ntp++) {
                uint32_t t0, t1, t2, t3;
                ldsm_x4(t0, t1, t2, t3, sb + (uint32_t)(16 * ntp * GM_PAD + kk) * 4);
                b[2*ntp][0] = t0; b[2*ntp][1] = t1;
                b[2*ntp+1][0] = t2; b[2*ntp+1][1] = t3;
            }
            #pragma unroll
            for (int mt = 0; mt < 4; mt++)
                #pragma unroll
                for (int nt = 0; nt < 4; nt++)
                    mma_tf32(acc[mt][nt], a[mt], b[nt]);
        }
    }

    // epilogue
    #pragma unroll
    for (int mt = 0; mt < 4; mt++) {
        #pragma unroll
        for (int nt = 0; nt < 4; nt++) {
            int r = m0 + 64 * wm + 16 * mt + g;
            int c = n0 + 32 * wn + 8 * nt + 2 * qd;
            if (cmode == 0) {
                #pragma unroll
                for (int hf = 0; hf < 2; hf++) {
                    int rr = r + hf * 8;
                    *(float2*)&C[(size_t)rr * N + c] =
                        make_float2(acc[mt][nt][2*hf], acc[mt][nt][2*hf+1]);
                }
            } else if (c < D_MODEL) {
                // Q with RoPE -> g_Q[h][t][d]
                int i = (c & 127) >> 1;
                float omega = (float)(1.0 / pow(10000.0, (double)(2 * i) / (double)DH));
                #pragma unroll
                for (int hf = 0; hf < 2; hf++) {
                    int rr = r + hf * 8;
                    float s, co;
                    sincosf((float)rr * omega, &s, &co);
                    float v0 = acc[mt][nt][2*hf], v1 = acc[mt][nt][2*hf+1];
                    size_t base = ((size_t)(c >> 7) * T_SEQ + rr) * 128 + (c & 127);
                    *(float2*)&g_Q[base] =
                        make_float2(to_tf32(v0 * co - v1 * s), to_tf32(v0 * s + v1 * co));
                }
            } else if (c < D_MODEL + DKV) {
                // K with RoPE -> g_K[kh][t][d] (t-major)
                int d  = c - D_MODEL;
                int kh = d >> 7;
                int dd = d & 127;
                int i  = dd >> 1;
                float omega = (float)(1.0 / pow(10000.0, (double)(2 * i) / (double)DH));
                #pragma unroll
                for (int hf = 0; hf < 2; hf++) {
                    int rr = r + hf * 8;
                    float s, co;
                    sincosf((float)rr * omega, &s, &co);
                    float v0 = acc[mt][nt][2*hf], v1 = acc[mt][nt][2*hf+1];
                    size_t base = ((size_t)kh * T_SEQ + rr) * 128 + dd;
                    *(float2*)&g_K[base] =
                        make_float2(to_tf32(v0 * co - v1 * s), to_tf32(v0 * s + v1 * co));
                }
            } else {
                // V -> g_V[kh][d][t] (d-major)
                int d  = c - (D_MODEL + DKV);
                int kh = d >> 7;
                int dd = d & 127;
                #pragma unroll
                for (int hf = 0; hf < 2; hf++) {
                    int rr = r + hf * 8;
                    size_t base = ((size_t)kh * DH + dd) * T_SEQ + rr;
                    g_V[base]         = to_tf32(acc[mt][nt][2*hf]);
                    g_V[base + T_SEQ] = to_tf32(acc[mt][nt][2*hf+1]);
                }
            }
        }
    }
}

// ---------------------------------------------------------------------------
// Batched weight transpose + tf32 rounding: one launch for WQ/WK/WV/WO.
// ---------------------------------------------------------------------------
__global__ void transpose_rnd4(const float* __restrict__ WQ, const float* __restrict__ WK,
                               const float* __restrict__ WV, const float* __restrict__ WO)
{
    __shared__ float t[32][33];
    int z = blockIdx.z;
    const float* src;
    float* dst;
    int N;
    if (z == 0)      { src = WQ; dst = g_Wqkv;                              N = D_MODEL; }
    else if (z == 1) { src = WK; dst = g_Wqkv + (size_t)D_MODEL * D_MODEL;  N = DKV; }
    else if (z == 2) { src = WV; dst = g_Wqkv + (size_t)(D_MODEL + DKV) * D_MODEL; N = DKV; }
    else             { src = WO; dst = g_WOt;                               N = D_MODEL; }

    int n0 = blockIdx.x * 32;
    if (n0 >= N) return;
    int k0 = blockIdx.y * 32;
    #pragma unroll
    for (int i = threadIdx.y; i < 32; i += 8)
        t[i][threadIdx.x] = src[(size_t)(k0 + i) * N + n0 + threadIdx.x];
    __syncthreads();
    #pragma unroll
    for (int i = threadIdx.y; i < 32; i += 8)
        dst[(size_t)(n0 + i) * D_MODEL + k0 + threadIdx.x] = to_tf32(t[threadIdx.x][i]);
}

__global__ void round_tf32_kernel(const float4* __restrict__ in, float4* __restrict__ out, int n4)
{
    int i = blockIdx.x * blockDim.x + threadIdx.x;
    if (i < n4) {
        float4 v = in[i];
        v.x = to_tf32(v.x); v.y = to_tf32(v.y);
        v.z = to_tf32(v.z); v.w = to_tf32(v.w);
        out[i] = v;
    }
}

// ---------------------------------------------------------------------------
// Flash attention (mma.sync tf32 + ldmatrix). q-tile 128, kv-tile 64,
// 256 thr (8 warps), warp owns 16 q-rows (softmax warp-local).
// Smem: Ks[2][64][132] (t-major), Vs[2][128][68] (d-major), Ps[128][68].
// Q fragments in registers (loaded once via ldmatrix from staged smem,
// staging area aliases the two K buffers). One __syncthreads per kv-tile.
// ---------------------------------------------------------------------------
#define KVPAD 132
#define VPAD2 68
#define PPAD  68
#define FL_KS_F 0
#define FL_VS_F (2 * 64 * KVPAD)                       // 16896
#define FL_PS_F (FL_VS_F + 2 * 128 * VPAD2)            // 34304
#define FL_SMEM ((FL_PS_F + 128 * PPAD) * 4)           // 172,032 B

__device__ __forceinline__ void fl_load_kv(
    const float* __restrict__ Kh, const float* __restrict__ Vh,
    uint32_t kdst, uint32_t vdst, int kbase, int tid)
{
    #pragma unroll
    for (int it = 0; it < 8; it++) {       // K tile: [t=64][d=128] rows
        int idx = it * 256 + tid;
        int r = idx >> 5, c = (idx & 31) << 2;
        cp_async16(kdst + (uint32_t)(r * KVPAD + c) * 4,
                   Kh + (size_t)(kbase + r) * DH + c);
    }
    #pragma unroll
    for (int it = 0; it < 8; it++) {       // V tile: [d=128][t=64] rows
        int idx = it * 256 + tid;
        int r = idx >> 4, c = (idx & 15) << 2;
        cp_async16(vdst + (uint32_t)(r * VPAD2 + c) * 4,
                   Vh + (size_t)r * T_SEQ + kbase + c);
    }
}

__global__ __launch_bounds__(256, 1)
void flash_mma(const float* __restrict__ Qg, const float* __restrict__ Kg,
               const float* __restrict__ Vg, float* __restrict__ Ctx)
{
    extern __shared__ __align__(16) float sm[];
    float* Ps = sm + FL_PS_F;

    const int tid  = threadIdx.x;
    const int w    = tid >> 5;
    const int lane = tid & 31;
    const int g    = lane >> 2;
    const int qd   = lane & 3;
    const int lm   = lane >> 3;
    const int lr   = lane & 7;
    const int qt   = gridDim.x - 1 - blockIdx.x;   // big tiles first
    const int h    = blockIdx.y;
    const int kh   = h >> 2;
    const int qbase = qt * 128;
    const int r0   = 16 * w + g;

    const float* Qh = Qg + (size_t)h * T_SEQ * DH;
    const float* Kh = Kg + (size_t)kh * T_SEQ * DH;   // [t][d]
    const float* Vh = Vg + (size_t)kh * DH * T_SEQ;   // [d][t]

    const uint32_t smu = smem_to_u32(sm);
    const uint32_t ksu = smu;
    const uint32_t vsu = smu + FL_VS_F * 4;
    const uint32_t psu = smu + FL_PS_F * 4;

    // 1) stage Q into the K-buffer area as [128][KVPAD]
    #pragma unroll
    for (int it = 0; it < 16; it++) {
        int idx = it * 256 + tid;
        int r = idx >> 5, c = (idx & 31) << 2;
        *(float4*)&sm[r * KVPAD + c] = *(const float4*)&Qh[(size_t)(qbase + r) * DH + c];
    }
    __syncthreads();

    // 2) Q fragments via ldmatrix (A-fragment layout)
    uint32_t qf[16][4];
    {
        uint32_t qlane = smu + (uint32_t)(((16 * w + (lm & 1) * 8 + lr) * KVPAD)
                                          + (lm >> 1) * 4) * 4;
        #pragma unroll
        for (int kk = 0; kk < 16; kk++)
            ldsm_x4(qf[kk][0], qf[kk][1], qf[kk][2], qf[kk][3], qlane + kk * 32);
    }
    __syncthreads();   // Q reads done before K prefetch overwrites

    const int ntiles = 2 * qt + 2;

    // 3) prologue: K(0), V(0)
    fl_load_kv(Kh, Vh, ksu, vsu, 0, tid);
    CP_COMMIT();

    float m_i[2] = {-1e30f, -1e30f};
    float l_i[2] = {0.f, 0.f};
    float o[16][4];
    #pragma unroll
    for (int nt = 0; nt < 16; nt++)
        #pragma unroll
        for (int e = 0; e < 4; e++) o[nt][e] = 0.f;

    const float SCALE = 0.08838834764831843f;   // 1/sqrt(128)

    // per-lane ldmatrix offsets
    const uint32_t kOffL = (uint32_t)((((lm >> 1) * 8 + lr) * KVPAD) + (lm & 1) * 4) * 4;
    const uint32_t vOffL = (uint32_t)((((lm >> 1) * 8 + lr) * VPAD2) + (lm & 1) * 4) * 4;
    const uint32_t pOffL = (uint32_t)(((16 * w + (lm & 1) * 8 + lr) * PPAD)
                                      + (lm >> 1) * 4) * 4;

    for (int jt = 0; jt < ntiles; jt++) {
        CP_WAIT_0();
        __syncthreads();

        if (jt + 1 < ntiles) {
            uint32_t kdst = ksu + (uint32_t)(((jt + 1) & 1) * 64 * KVPAD) * 4;
            uint32_t vdst = vsu + (uint32_t)(((jt + 1) & 1) * 128 * VPAD2) * 4;
            fl_load_kv(Kh, Vh, kdst, vdst, (jt + 1) * 64, tid);
            CP_COMMIT();
        }

        const int kbase = jt * 64;
        const uint32_t kb = ksu + (uint32_t)((jt & 1) * 64 * KVPAD) * 4 + kOffL;
        const uint32_t vb = vsu + (uint32_t)((jt & 1) * 128 * VPAD2) * 4 + vOffL;

        // S = Q @ K^T
        float s[8][4];
        #pragma unroll
        for (int nt = 0; nt < 8; nt++)
            #pragma unroll
            for (int e = 0; e < 4; e++) s[nt][e] = 0.f;

        #pragma unroll
        for (int kk = 0; kk < 16; kk++) {
            #pragma unroll
            for (int ntp = 0; ntp < 4; ntp++) {
                uint32_t b0, b1, b2, b3;
                ldsm_x4(b0, b1, b2, b3,
                        kb + (uint32_t)(ntp * 16 * KVPAD + kk * 8) * 4);
                uint32_t bb0[2] = {b0, b1};
                uint32_t bb1[2] = {b2, b3};
                mma_tf32(s[2*ntp],     qf[kk], bb0);
                mma_tf32(s[2*ntp + 1], qf[kk], bb1);
            }
        }

        #pragma unroll
        for (int nt = 0; nt < 8; nt++)
            #pragma unroll
            for (int e = 0; e < 4; e++) s[nt][e] *= SCALE;

        if (jt >= 2 * qt) {   // diagonal region: mask col > row
            #pragma unroll
            for (int nt = 0; nt < 8; nt++)
                #pragma unroll
                for (int e = 0; e < 4; e++) {
                    int col = kbase + nt * 8 + 2 * qd + (e & 1);
                    int row = qbase + r0 + ((e >> 1) << 3);
                    if (col > row) s[nt][e] = -1e30f;
                }
        }

        // online softmax (rows r0: e0,e1; r0+8: e2,e3) — quad shfl reduce
        float mx0 = -1e30f, mx1 = -1e30f;
        #pragma unroll
        for (int nt = 0; nt < 8; nt++) {
            mx0 = fmaxf(mx0, fmaxf(s[nt][0], s[nt][1]));
            mx1 = fmaxf(mx1, fmaxf(s[nt][2], s[nt][3]));
        }
        mx0 = fmaxf(mx0, __shfl_xor_sync(0xffffffffu, mx0, 1));
        mx0 = fmaxf(mx0, __shfl_xor_sync(0xffffffffu, mx0, 2));
        mx1 = fmaxf(mx1, __shfl_xor_sync(0xffffffffu, mx1, 1));
        mx1 = fmaxf(mx1, __shfl_xor_sync(0xffffffffu, mx1, 2));
        float mn0 = fmaxf(m_i[0], mx0);
        float mn1 = fmaxf(m_i[1], mx1);
        float sc0 = __expf(m_i[0] - mn0);
        float sc1 = __expf(m_i[1] - mn1);
        m_i[0] = mn0; m_i[1] = mn1;

        float rs0 = 0.f, rs1 = 0.f;
        #pragma unroll
        for (int nt = 0; nt < 8; nt++) {
            s[nt][0] = __expf(s[nt][0] - mn0);
            s[nt][1] = __expf(s[nt][1] - mn0);
            s[nt][2] = __expf(s[nt][2] - mn1);
            s[nt][3] = __expf(s[nt][3] - mn1);
            rs0 += s[nt][0] + s[nt][1];
            rs1 += s[nt][2] + s[nt][3];
        }
        rs0 += __shfl_xor_sync(0xffffffffu, rs0, 1);
        rs0 += __shfl_xor_sync(0xffffffffu, rs0, 2);
        rs1 += __shfl_xor_sync(0xffffffffu, rs1, 1);
        rs1 += __shfl_xor_sync(0xffffffffu, rs1, 2);
        l_i[0] = l_i[0] * sc0 + rs0;
        l_i[1] = l_i[1] * sc1 + rs1;

        #pragma unroll
        for (int nt = 0; nt < 16; nt++) {
            o[nt][0] *= sc0; o[nt][1] *= sc0;
            o[nt][2] *= sc1; o[nt][3] *= sc1;
        }
        // stage P (rounded) — warp-private rows
        #pragma unroll
        for (int nt = 0; nt < 8; nt++) {
            *(float2*)&Ps[(r0    ) * PPAD + nt * 8 + 2 * qd] =
                make_float2(to_tf32(s[nt][0]), to_tf32(s[nt][1]));
            *(float2*)&Ps[(r0 + 8) * PPAD + nt * 8 + 2 * qd] =
                make_float2(to_tf32(s[nt][2]), to_tf32(s[nt][3]));
        }
        __syncwarp();

        // O += P @ V
        #pragma unroll
        for (int kk = 0; kk < 8; kk++) {
            uint32_t a[4];
            ldsm_x4(a[0], a[1], a[2], a[3], psu + pOffL + kk * 32);
            #pragma unroll
            for (int ntp = 0; ntp < 8; ntp++) {
                uint32_t b0, b1, b2, b3;
                ldsm_x4(b0, b1, b2, b3,
                        vb + (uint32_t)(ntp * 16 * VPAD2 + kk * 8) * 4);
                uint32_t bb0[2] = {b0, b1};
                uint32_t bb1[2] = {b2, b3};
                mma_tf32(o[2*ntp],     a, bb0);
                mma_tf32(o[2*ntp + 1], a, bb1);
            }
        }
    }

    // epilogue: normalize, round to tf32 (feeds O-projection), write ctx
    float inv0 = 1.0f / l_i[0];
    float inv1 = 1.0f / l_i[1];
    #pragma unroll
    for (int nt = 0; nt < 16; nt++) {
        size_t b0 = (size_t)(qbase + r0    ) * D_MODEL + h * DH + nt * 8 + 2 * qd;
        size_t b1 = (size_t)(qbase + r0 + 8) * D_MODEL + h * DH + nt * 8 + 2 * qd;
        *(float2*)&Ctx[b0] = make_float2(to_tf32(o[nt][0] * inv0), to_tf32(o[nt][1] * inv0));
        *(float2*)&Ctx[b1] = make_float2(to_tf32(o[nt][2] * inv1), to_tf32(o[nt][3] * inv1));
    }
}

// ---------------------------------------------------------------------------
// kernel_launch
// ---------------------------------------------------------------------------
extern "C" void kernel_launch(void* const* d_in, const int* in_sizes, int n_in,
                              void* d_out, int out_size)
{
    const float* x  = (const float*)d_in[0];
    const float* WQ = (const float*)d_in[1];
    const float* WK = (const float*)d_in[2];
    const float* WV = (const float*)d_in[3];
    const float* WO = (const float*)d_in[4];
    float* out = (float*)d_out;

    float *qp, *kp, *vp, *cp, *xr, *wqkv, *wot;
    cudaGetSymbolAddress((void**)&qp,   g_Q);
    cudaGetSymbolAddress((void**)&kp,   g_K);
    cudaGetSymbolAddress((void**)&vp,   g_V);
    cudaGetSymbolAddress((void**)&cp,   g_C);
    cudaGetSymbolAddress((void**)&xr,   g_Xr);
    cudaGetSymbolAddress((void**)&wqkv, g_Wqkv);
    cudaGetSymbolAddress((void**)&wot,  g_WOt);

    cudaFuncSetAttribute(flash_mma,
                         cudaFuncAttributeMaxDynamicSharedMemorySize, FL_SMEM);
    cudaFuncSetAttribute(gemm_mma,
                         cudaFuncAttributeMaxDynamicSharedMemorySize, GM_SMEM);

    // 1) round x to tf32 (RNA)
    {
        int n4 = T_SEQ * D_MODEL / 4;
        round_tf32_kernel<<<(n4 + 255) / 256, 256>>>((const float4*)x, (float4*)xr, n4);
    }
    // 2) all weight transposes in one launch
    transpose_rnd4<<<dim3(64, 64, 4), dim3(32, 8)>>>(WQ, WK, WV, WO);

    // 3) fused QKV projection (epilogue applies RoPE + layouts)
    gemm_mma<<<dim3(NQKV/128, T_SEQ/128), 256, GM_SMEM>>>(xr, wqkv, nullptr,
                                                          T_SEQ, NQKV, D_MODEL, 3);

    // 4) attention
    flash_mma<<<dim3(T_SEQ/128, NH), 256, FL_SMEM>>>(qp, kp, vp, cp);

    // 5) output projection
    gemm_mma<<<dim3(D_MODEL/128, T_SEQ/128), 256, GM_SMEM>>>(cp, wot, out,
                                                             T_SEQ, D_MODEL, D_MODEL, 0);
}

// round 10
// speedup vs baseline: 1.7619x; 1.6612x over previous
#include <cuda_runtime.h>
#include <cuda_fp16.h>
#include <math.h>
#include <stdint.h>

// Problem constants
#define T_SEQ 4096
#define D_MODEL 2048
#define DH 128
#define NH 16
#define NKV 4
#define DKV 512   // NKV * DH
#define NQKV 3072 // D_MODEL + 2*DKV

// ---------------------------------------------------------------------------
// Scratch (device globals — no allocations allowed)
// ---------------------------------------------------------------------------
__device__ __half g_Q[(size_t)NH * T_SEQ * DH];    // [h][t][d]  roped fp16
__device__ __half g_K[(size_t)NKV * T_SEQ * DH];   // [kh][t][d] roped fp16
__device__ __half g_V[(size_t)NKV * DH * T_SEQ];   // [kh][d][t] fp16
__device__ __half g_C[(size_t)T_SEQ * D_MODEL];    // ctx [t][h*128+d] fp16
__device__ __half g_Xh[(size_t)T_SEQ * D_MODEL];   // x rounded to fp16
__device__ __half g_Wqkv[(size_t)NQKV * D_MODEL];  // [WQ^T;WK^T;WV^T] [n][k] fp16
__device__ __half g_WOt[(size_t)D_MODEL * D_MODEL];// WO^T [n][k] fp16

// ---------------------------------------------------------------------------
// Helpers (sm_80-era PTX: mma.sync, ldmatrix, cp.async, shfl)
// ---------------------------------------------------------------------------
__device__ __forceinline__ uint32_t smem_to_u32(const void* p) {
    uint32_t a;
    asm("{ .reg .u64 t; cvta.to.shared.u64 t, %1; cvt.u32.u64 %0, t; }"
        : "=r"(a) : "l"(p));
    return a;
}

__device__ __forceinline__ void cp_async16(uint32_t saddr, const void* g) {
    asm volatile("cp.async.cg.shared.global [%0], [%1], 16;" :: "r"(saddr), "l"(g));
}
#define CP_COMMIT() asm volatile("cp.async.commit_group;" ::: "memory")
#define CP_WAIT_0() asm volatile("cp.async.wait_group 0;" ::: "memory")
#define CP_WAIT_1() asm volatile("cp.async.wait_group 1;" ::: "memory")

// fp16: D += A(16x16) * B(16x8), fp32 accumulate
__device__ __forceinline__ void mma_f16(float* d, const uint32_t* a, const uint32_t* b) {
    asm volatile(
        "mma.sync.aligned.m16n8k16.row.col.f32.f16.f16.f32 "
        "{%0,%1,%2,%3}, {%4,%5,%6,%7}, {%8,%9}, {%0,%1,%2,%3};"
        : "+f"(d[0]), "+f"(d[1]), "+f"(d[2]), "+f"(d[3])
        : "r"(a[0]), "r"(a[1]), "r"(a[2]), "r"(a[3]), "r"(b[0]), "r"(b[1]));
}

__device__ __forceinline__ void ldsm_x4(uint32_t& r0, uint32_t& r1,
                                        uint32_t& r2, uint32_t& r3, uint32_t addr) {
    asm volatile("ldmatrix.sync.aligned.m8n8.x4.shared.b16 {%0,%1,%2,%3}, [%4];"
                 : "=r"(r0), "=r"(r1), "=r"(r2), "=r"(r3) : "r"(addr));
}

// ---------------------------------------------------------------------------
// GEMM (fp16 mma.sync m16n8k16 + ldmatrix): C[M,N] = A[M,K] @ Bt[N,K]^T
//   128x128 tile, 256 thr, warp grid 2m x 4n (warp 64x32), K-tile 32,
//   3-stage cp.async pipeline, 2 CTAs/SM.
//   cmode 0: row-major fp32 C (O-projection output).
//   cmode 3: fused QKV epilogue + RoPE -> fp16 layouts.
// ---------------------------------------------------------------------------
#define GM_KT 32
#define GM_ROW 40                         // fp16 per smem row (32 data + 8 pad), 80B
#define GM_STG 3
#define GM_STAGE_B (128 * GM_ROW * 2)     // one matrix: 10,240 B
#define GM_SMEM (GM_STG * GM_STAGE_B * 2) // 61,440 B

__device__ __forceinline__ void gm_load_stage(
    const __half* __restrict__ A, const __half* __restrict__ Bt,
    uint32_t sA, uint32_t sB, int kt, int K, int tid)
{
    #pragma unroll
    for (int it = 0; it < 2; it++) {
        int idx = it * 256 + tid;
        int row = idx >> 2;           // 0..127
        int c   = idx & 3;            // 16B chunk (8 fp16)
        uint32_t off = (uint32_t)(row * GM_ROW * 2 + c * 16);
        cp_async16(sA + off, A  + (size_t)row * K + kt * GM_KT + c * 8);
        cp_async16(sB + off, Bt + (size_t)row * K + kt * GM_KT + c * 8);
    }
}

__global__ __launch_bounds__(256, 2)
void gemm_mma(const __half* __restrict__ A, const __half* __restrict__ Bt,
              float* __restrict__ C, int M, int N, int K, int cmode)
{
    extern __shared__ __align__(16) char gsmc[];
    const uint32_t sAu = smem_to_u32(gsmc);
    const uint32_t sBu = sAu + GM_STG * GM_STAGE_B;

    const int tid  = threadIdx.x;
    const int w    = tid >> 5;
    const int lane = tid & 31;
    const int g    = lane >> 2;
    const int qd   = lane & 3;
    const int lr   = lane & 7;
    const int wm   = w & 1;
    const int wn   = w >> 1;
    const int m0   = blockIdx.y * 128;
    const int n0   = blockIdx.x * 128;
    const int NKT  = K / GM_KT;

    const __half* Ab = A  + (size_t)m0 * K;
    const __half* Bb = Bt + (size_t)n0 * K;

    // ldmatrix lane selectors (b16)
    const uint32_t aSel = ((lane >> 3) & 1);
    const uint32_t aCol = ((lane >> 4) & 1);
    const uint32_t bSel = ((lane >> 4) & 1);
    const uint32_t bCol = ((lane >> 3) & 1);

    const uint32_t aOffL = (uint32_t)((aSel * 8 + lr) + 64 * wm) * (GM_ROW * 2) + aCol * 16;
    const uint32_t bOffL = (uint32_t)((bSel * 8 + lr) + 32 * wn) * (GM_ROW * 2) + bCol * 16;

    float acc[4][4][4];
    #pragma unroll
    for (int mt = 0; mt < 4; mt++)
        #pragma unroll
        for (int nt = 0; nt < 4; nt++)
            #pragma unroll
            for (int e = 0; e < 4; e++) acc[mt][nt][e] = 0.f;

    gm_load_stage(Ab, Bb, sAu, sBu, 0, K, tid); CP_COMMIT();
    gm_load_stage(Ab, Bb, sAu + GM_STAGE_B, sBu + GM_STAGE_B, 1, K, tid); CP_COMMIT();

    for (int kt = 0; kt < NKT; kt++) {
        CP_WAIT_1();
        __syncthreads();
        if (kt + 2 < NKT) {
            int s2 = (kt + 2) % GM_STG;
            gm_load_stage(Ab, Bb, sAu + s2 * GM_STAGE_B, sBu + s2 * GM_STAGE_B,
                          kt + 2, K, tid);
            CP_COMMIT();
        }
        uint32_t sa = sAu + (kt % GM_STG) * GM_STAGE_B + aOffL;
        uint32_t sb = sBu + (kt % GM_STG) * GM_STAGE_B + bOffL;

        #pragma unroll
        for (int ks = 0; ks < 2; ks++) {        // two k16 steps per K-tile
            uint32_t a[4][4];
            #pragma unroll
            for (int mt = 0; mt < 4; mt++)
                ldsm_x4(a[mt][0], a[mt][1], a[mt][2], a[mt][3],
                        sa + (uint32_t)(16 * mt * GM_ROW * 2) + ks * 32);
            uint32_t b[4][2];
            #pragma unroll
            for (int ntp = 0; ntp < 2; ntp++) {
                uint32_t t0, t1, t2, t3;
                ldsm_x4(t0, t1, t2, t3,
                        sb + (uint32_t)(16 * ntp * GM_ROW * 2) + ks * 32);
                b[2*ntp][0] = t0; b[2*ntp][1] = t1;
                b[2*ntp+1][0] = t2; b[2*ntp+1][1] = t3;
            }
            #pragma unroll
            for (int mt = 0; mt < 4; mt++)
                #pragma unroll
                for (int nt = 0; nt < 4; nt++)
                    mma_f16(acc[mt][nt], a[mt], b[nt]);
        }
    }

    // epilogue
    #pragma unroll
    for (int mt = 0; mt < 4; mt++) {
        #pragma unroll
        for (int nt = 0; nt < 4; nt++) {
            int r = m0 + 64 * wm + 16 * mt + g;
            int c = n0 + 32 * wn + 8 * nt + 2 * qd;
            if (cmode == 0) {
                #pragma unroll
                for (int hf = 0; hf < 2; hf++) {
                    int rr = r + hf * 8;
                    *(float2*)&C[(size_t)rr * N + c] =
                        make_float2(acc[mt][nt][2*hf], acc[mt][nt][2*hf+1]);
                }
            } else if (c < D_MODEL) {
                // Q + RoPE -> g_Q[h][t][d] fp16
                int i = (c & 127) >> 1;
                float omega = (float)(1.0 / pow(10000.0, (double)(2 * i) / (double)DH));
                #pragma unroll
                for (int hf = 0; hf < 2; hf++) {
                    int rr = r + hf * 8;
                    float s, co;
                    sincosf((float)rr * omega, &s, &co);
                    float v0 = acc[mt][nt][2*hf], v1 = acc[mt][nt][2*hf+1];
                    size_t base = ((size_t)(c >> 7) * T_SEQ + rr) * 128 + (c & 127);
                    *(__half2*)&g_Q[base] =
                        __floats2half2_rn(v0 * co - v1 * s, v0 * s + v1 * co);
                }
            } else if (c < D_MODEL + DKV) {
                // K + RoPE -> g_K[kh][t][d] fp16
                int d  = c - D_MODEL;
                int kh = d >> 7;
                int dd = d & 127;
                int i  = dd >> 1;
                float omega = (float)(1.0 / pow(10000.0, (double)(2 * i) / (double)DH));
                #pragma unroll
                for (int hf = 0; hf < 2; hf++) {
                    int rr = r + hf * 8;
                    float s, co;
                    sincosf((float)rr * omega, &s, &co);
                    float v0 = acc[mt][nt][2*hf], v1 = acc[mt][nt][2*hf+1];
                    size_t base = ((size_t)kh * T_SEQ + rr) * 128 + dd;
                    *(__half2*)&g_K[base] =
                        __floats2half2_rn(v0 * co - v1 * s, v0 * s + v1 * co);
                }
            } else {
                // V -> g_V[kh][d][t] fp16 (d-major)
                int d  = c - (D_MODEL + DKV);
                int kh = d >> 7;
                int dd = d & 127;
                #pragma unroll
                for (int hf = 0; hf < 2; hf++) {
                    int rr = r + hf * 8;
                    size_t base = ((size_t)kh * DH + dd) * T_SEQ + rr;
                    g_V[base]         = __float2half_rn(acc[mt][nt][2*hf]);
                    g_V[base + T_SEQ] = __float2half_rn(acc[mt][nt][2*hf+1]);
                }
            }
        }
    }
}

// ---------------------------------------------------------------------------
// Batched weight transpose + fp16 rounding: Wt[n][k] = fp16(W[k][n])
// ---------------------------------------------------------------------------
__global__ void transpose_rnd4(const float* __restrict__ WQ, const float* __restrict__ WK,
                               const float* __restrict__ WV, const float* __restrict__ WO)
{
    __shared__ float t[32][33];
    int z = blockIdx.z;
    const float* src;
    __half* dst;
    int N;
    if (z == 0)      { src = WQ; dst = g_Wqkv;                              N = D_MODEL; }
    else if (z == 1) { src = WK; dst = g_Wqkv + (size_t)D_MODEL * D_MODEL;  N = DKV; }
    else if (z == 2) { src = WV; dst = g_Wqkv + (size_t)(D_MODEL + DKV) * D_MODEL; N = DKV; }
    else             { src = WO; dst = g_WOt;                               N = D_MODEL; }

    int n0 = blockIdx.x * 32;
    if (n0 >= N) return;
    int k0 = blockIdx.y * 32;
    #pragma unroll
    for (int i = threadIdx.y; i < 32; i += 8)
        t[i][threadIdx.x] = src[(size_t)(k0 + i) * N + n0 + threadIdx.x];
    __syncthreads();
    #pragma unroll
    for (int i = threadIdx.y; i < 32; i += 8)
        dst[(size_t)(n0 + i) * D_MODEL + k0 + threadIdx.x] =
            __float2half_rn(t[threadIdx.x][i]);
}

// x fp32 -> fp16
__global__ void round_fp16_kernel(const float4* __restrict__ in, __half2* __restrict__ out, int n4)
{
    int i = blockIdx.x * blockDim.x + threadIdx.x;
    if (i < n4) {
        float4 v = in[i];
        out[2*i]     = __floats2half2_rn(v.x, v.y);
        out[2*i + 1] = __floats2half2_rn(v.z, v.w);
    }
}

// ---------------------------------------------------------------------------
// Flash attention, fp16 mma.sync (m16n8k16) + native b16 ldmatrix.
// q-tile 128, kv-tile 64, 256 thr (8 warps), warp owns 16 q-rows.
// Smem (bytes): K[2][64 x 272B] | V[2][128 x 144B] | P[128 x 144B].
// Q staged in K area, fragments cached in registers. One barrier per kv-tile.
// (identical layout to the functionally-verified round-8 kernel; dtype fp16)
// ---------------------------------------------------------------------------
#define KROW_B 272                    // 128 fp16 + 8 pad
#define VROW_B 144                    // 64 fp16 + 8 pad
#define PROW_B 144
#define KBUF_B (64 * KROW_B)          // 17408
#define VBUF_B (128 * VROW_B)         // 18432
#define PS_OFF (2 * KBUF_B + 2 * VBUF_B)
#define FL_SMEM (PS_OFF + 128 * PROW_B)   // 90,112 B

__device__ __forceinline__ void fl_load_kv(
    const __half* __restrict__ Kh, const __half* __restrict__ Vh,
    uint32_t kdst, uint32_t vdst, int kbase, int tid)
{
    #pragma unroll
    for (int it = 0; it < 4; it++) {       // K tile: 64 rows x 256B
        int idx = it * 256 + tid;
        int r = idx >> 4, c = idx & 15;
        cp_async16(kdst + (uint32_t)(r * KROW_B + c * 16),
                   Kh + (size_t)(kbase + r) * DH + c * 8);
    }
    #pragma unroll
    for (int it = 0; it < 4; it++) {       // V tile: 128 rows x 128B
        int idx = it * 256 + tid;
        int r = idx >> 3, c = idx & 7;
        cp_async16(vdst + (uint32_t)(r * VROW_B + c * 16),
                   Vh + (size_t)r * T_SEQ + kbase + c * 8);
    }
}

__global__ __launch_bounds__(256, 1)
void flash_mma(const __half* __restrict__ Qg, const __half* __restrict__ Kg,
               const __half* __restrict__ Vg, __half* __restrict__ Ctx)
{
    extern __shared__ __align__(16) char smc[];
    __half* Ps = (__half*)(smc + PS_OFF);

    const int tid  = threadIdx.x;
    const int w    = tid >> 5;
    const int lane = tid & 31;
    const int g    = lane >> 2;
    const int qd   = lane & 3;
    const int qt   = gridDim.x - 1 - blockIdx.x;   // big tiles first
    const int h    = blockIdx.y;
    const int kh   = h >> 2;
    const int qbase = qt * 128;
    const int r0   = 16 * w + g;

    const __half* Qh = Qg + (size_t)h * T_SEQ * DH;
    const __half* Kh = Kg + (size_t)kh * T_SEQ * DH;   // [t][d]
    const __half* Vh = Vg + (size_t)kh * DH * T_SEQ;   // [d][t]

    const uint32_t smu = smem_to_u32(smc);
    const uint32_t ksu = smu;
    const uint32_t vsu = smu + 2 * KBUF_B;
    const uint32_t psu = smu + PS_OFF;

    // ldmatrix lane selectors
    const uint32_t aSel = ((lane >> 3) & 1);
    const uint32_t aCol = ((lane >> 4) & 1);
    const uint32_t bSel = ((lane >> 4) & 1);
    const uint32_t bCol = ((lane >> 3) & 1);
    const int      lr   = lane & 7;

    const uint32_t qOffL = (uint32_t)(16 * w + aSel * 8 + lr) * KROW_B + aCol * 16;
    const uint32_t kOffL = (uint32_t)(bSel * 8 + lr) * KROW_B + bCol * 16;
    const uint32_t vOffL = (uint32_t)(bSel * 8 + lr) * VROW_B + bCol * 16;
    const uint32_t pOffL = (uint32_t)(16 * w + aSel * 8 + lr) * PROW_B + aCol * 16;

    // 1) stage Q (fp16) into the K-buffer area
    #pragma unroll
    for (int it = 0; it < 8; it++) {
        int idx = it * 256 + tid;
        int r = idx >> 4, c = idx & 15;
        cp_async16(ksu + (uint32_t)(r * KROW_B + c * 16),
                   Qh + (size_t)(qbase + r) * DH + c * 8);
    }
    CP_COMMIT();
    CP_WAIT_0();
    __syncthreads();

    // 2) Q fragments (8 x k16) via ldmatrix
    uint32_t qf[8][4];
    #pragma unroll
    for (int kk = 0; kk < 8; kk++)
        ldsm_x4(qf[kk][0], qf[kk][1], qf[kk][2], qf[kk][3],
                ksu + qOffL + kk * 32);
    __syncthreads();   // Q reads done before K(0) overwrites

    const int ntiles = 2 * qt + 2;

    // 3) prologue: K(0), V(0)
    fl_load_kv(Kh, Vh, ksu, vsu, 0, tid);
    CP_COMMIT();

    float m_i[2] = {-1e30f, -1e30f};
    float l_i[2] = {0.f, 0.f};
    float o[16][4];
    #pragma unroll
    for (int nt = 0; nt < 16; nt++)
        #pragma unroll
        for (int e = 0; e < 4; e++) o[nt][e] = 0.f;

    const float SCALE = 0.08838834764831843f;   // 1/sqrt(128)

    for (int jt = 0; jt < ntiles; jt++) {
        CP_WAIT_0();
        __syncthreads();

        if (jt + 1 < ntiles) {
            uint32_t kdst = ksu + ((jt + 1) & 1) * KBUF_B;
            uint32_t vdst = vsu + ((jt + 1) & 1) * VBUF_B;
            fl_load_kv(Kh, Vh, kdst, vdst, (jt + 1) * 64, tid);
            CP_COMMIT();
        }

        const int kbase = jt * 64;
        const uint32_t kb = ksu + (jt & 1) * KBUF_B + kOffL;
        const uint32_t vb = vsu + (jt & 1) * VBUF_B + vOffL;

        // S = Q @ K^T
        float s[8][4];
        #pragma unroll
        for (int nt = 0; nt < 8; nt++)
            #pragma unroll
            for (int e = 0; e < 4; e++) s[nt][e] = 0.f;

        #pragma unroll
        for (int kk = 0; kk < 8; kk++) {
            #pragma unroll
            for (int ntp = 0; ntp < 4; ntp++) {
                uint32_t b0, b1, b2, b3;
                ldsm_x4(b0, b1, b2, b3,
                        kb + (uint32_t)(ntp * 16 * KROW_B) + kk * 32);
                uint32_t bb0[2] = {b0, b1};
                uint32_t bb1[2] = {b2, b3};
                mma_f16(s[2*ntp],     qf[kk], bb0);
                mma_f16(s[2*ntp + 1], qf[kk], bb1);
            }
        }

        #pragma unroll
        for (int nt = 0; nt < 8; nt++)
            #pragma unroll
            for (int e = 0; e < 4; e++) s[nt][e] *= SCALE;

        if (jt >= 2 * qt) {   // diagonal region: mask col > row
            #pragma unroll
            for (int nt = 0; nt < 8; nt++)
                #pragma unroll
                for (int e = 0; e < 4; e++) {
                    int col = kbase + nt * 8 + 2 * qd + (e & 1);
                    int row = qbase + r0 + ((e >> 1) << 3);
                    if (col > row) s[nt][e] = -1e30f;
                }
        }

        // online softmax — quad shfl reduce
        float mx0 = -1e30f, mx1 = -1e30f;
        #pragma unroll
        for (int nt = 0; nt < 8; nt++) {
            mx0 = fmaxf(mx0, fmaxf(s[nt][0], s[nt][1]));
            mx1 = fmaxf(mx1, fmaxf(s[nt][2], s[nt][3]));
        }
        mx0 = fmaxf(mx0, __shfl_xor_sync(0xffffffffu, mx0, 1));
        mx0 = fmaxf(mx0, __shfl_xor_sync(0xffffffffu, mx0, 2));
        mx1 = fmaxf(mx1, __shfl_xor_sync(0xffffffffu, mx1, 1));
        mx1 = fmaxf(mx1, __shfl_xor_sync(0xffffffffu, mx1, 2));
        float mn0 = fmaxf(m_i[0], mx0);
        float mn1 = fmaxf(m_i[1], mx1);
        float sc0 = __expf(m_i[0] - mn0);
        float sc1 = __expf(m_i[1] - mn1);
        m_i[0] = mn0; m_i[1] = mn1;

        float rs0 = 0.f, rs1 = 0.f;
        #pragma unroll
        for (int nt = 0; nt < 8; nt++) {
            s[nt][0] = __expf(s[nt][0] - mn0);
            s[nt][1] = __expf(s[nt][1] - mn0);
            s[nt][2] = __expf(s[nt][2] - mn1);
            s[nt][3] = __expf(s[nt][3] - mn1);
            rs0 += s[nt][0] + s[nt][1];
            rs1 += s[nt][2] + s[nt][3];
        }
        rs0 += __shfl_xor_sync(0xffffffffu, rs0, 1);
        rs0 += __shfl_xor_sync(0xffffffffu, rs0, 2);
        rs1 += __shfl_xor_sync(0xffffffffu, rs1, 1);
        rs1 += __shfl_xor_sync(0xffffffffu, rs1, 2);
        l_i[0] = l_i[0] * sc0 + rs0;
        l_i[1] = l_i[1] * sc1 + rs1;

        #pragma unroll
        for (int nt = 0; nt < 16; nt++) {
            o[nt][0] *= sc0; o[nt][1] *= sc0;
            o[nt][2] *= sc1; o[nt][3] *= sc1;
        }
        // stage P as fp16 — warp-private rows
        #pragma unroll
        for (int nt = 0; nt < 8; nt++) {
            *(__half2*)&Ps[(r0    ) * (PROW_B/2) + nt * 8 + 2 * qd] =
                __floats2half2_rn(s[nt][0], s[nt][1]);
            *(__half2*)&Ps[(r0 + 8) * (PROW_B/2) + nt * 8 + 2 * qd] =
                __floats2half2_rn(s[nt][2], s[nt][3]);
        }
        __syncwarp();

        // O += P @ V   (4 x k16 over kv, 8 d-groups of 16)
        #pragma unroll
        for (int kk = 0; kk < 4; kk++) {
            uint32_t a[4];
            ldsm_x4(a[0], a[1], a[2], a[3], psu + pOffL + kk * 32);
            #pragma unroll
            for (int dg = 0; dg < 8; dg++) {
                uint32_t b0, b1, b2, b3;
                ldsm_x4(b0, b1, b2, b3,
                        vb + (uint32_t)(dg * 16 * VROW_B) + kk * 32);
                uint32_t bb0[2] = {b0, b1};
                uint32_t bb1[2] = {b2, b3};
                mma_f16(o[2*dg],     a, bb0);
                mma_f16(o[2*dg + 1], a, bb1);
            }
        }
    }

    // epilogue: normalize, write ctx as fp16 (feeds fp16 O-projection)
    float inv0 = 1.0f / l_i[0];
    float inv1 = 1.0f / l_i[1];
    #pragma unroll
    for (int nt = 0; nt < 16; nt++) {
        size_t b0 = (size_t)(qbase + r0    ) * D_MODEL + h * DH + nt * 8 + 2 * qd;
        size_t b1 = (size_t)(qbase + r0 + 8) * D_MODEL + h * DH + nt * 8 + 2 * qd;
        *(__half2*)&Ctx[b0] = __floats2half2_rn(o[nt][0] * inv0, o[nt][1] * inv0);
        *(__half2*)&Ctx[b1] = __floats2half2_rn(o[nt][2] * inv1, o[nt][3] * inv1);
    }
}

// ---------------------------------------------------------------------------
// kernel_launch
// ---------------------------------------------------------------------------
extern "C" void kernel_launch(void* const* d_in, const int* in_sizes, int n_in,
                              void* d_out, int out_size)
{
    const float* x  = (const float*)d_in[0];
    const float* WQ = (const float*)d_in[1];
    const float* WK = (const float*)d_in[2];
    const float* WV = (const float*)d_in[3];
    const float* WO = (const float*)d_in[4];
    float* out = (float*)d_out;

    __half *qp, *kp, *vp, *cp, *xh, *wqkv, *wot;
    cudaGetSymbolAddress((void**)&qp,   g_Q);
    cudaGetSymbolAddress((void**)&kp,   g_K);
    cudaGetSymbolAddress((void**)&vp,   g_V);
    cudaGetSymbolAddress((void**)&cp,   g_C);
    cudaGetSymbolAddress((void**)&xh,   g_Xh);
    cudaGetSymbolAddress((void**)&wqkv, g_Wqkv);
    cudaGetSymbolAddress((void**)&wot,  g_WOt);

    cudaFuncSetAttribute(flash_mma,
                         cudaFuncAttributeMaxDynamicSharedMemorySize, FL_SMEM);
    cudaFuncSetAttribute(gemm_mma,
                         cudaFuncAttributeMaxDynamicSharedMemorySize, GM_SMEM);

    // 1) round x to fp16
    {
        int n4 = T_SEQ * D_MODEL / 4;
        round_fp16_kernel<<<(n4 + 255) / 256, 256>>>((const float4*)x, (__half2*)xh, n4);
    }
    // 2) all weight transposes (fp16) in one launch
    transpose_rnd4<<<dim3(64, 64, 4), dim3(32, 8)>>>(WQ, WK, WV, WO);

    // 3) fused QKV projection (fp16 MMA; epilogue: RoPE + fp16 layouts)
    gemm_mma<<<dim3(NQKV/128, T_SEQ/128), 256, GM_SMEM>>>(xh, wqkv, nullptr,
                                                          T_SEQ, NQKV, D_MODEL, 3);

    // 4) attention (fp16 tensor cores)
    flash_mma<<<dim3(T_SEQ/128, NH), 256, FL_SMEM>>>(qp, kp, vp, cp);

    // 5) output projection (fp16 MMA, fp32 out)
    gemm_mma<<<dim3(D_MODEL/128, T_SEQ/128), 256, GM_SMEM>>>(cp, wot, out,
                                                             T_SEQ, D_MODEL, D_MODEL, 0);
}

// round 11
// speedup vs baseline: 1.8348x; 1.0414x over previous
#include <cuda_runtime.h>
#include <cuda_fp16.h>
#include <math.h>
#include <stdint.h>

// Problem constants
#define T_SEQ 4096
#define D_MODEL 2048
#define DH 128
#define NH 16
#define NKV 4
#define DKV 512   // NKV * DH
#define NQKV 3072 // D_MODEL + 2*DKV

// Q pre-scale: (1/sqrt(128)) * log2(e)  — folded so flash uses exp2f
#define QSCALE 0.12751743560f

// ---------------------------------------------------------------------------
// Scratch (device globals — no allocations allowed)
// ---------------------------------------------------------------------------
__device__ __half g_Q[(size_t)NH * T_SEQ * DH];    // [h][t][d]  roped, pre-scaled fp16
__device__ __half g_K[(size_t)NKV * T_SEQ * DH];   // [kh][t][d] roped fp16
__device__ __half g_V[(size_t)NKV * DH * T_SEQ];   // [kh][d][t] fp16
__device__ __half g_C[(size_t)T_SEQ * D_MODEL];    // ctx [t][h*128+d] fp16
__device__ __half g_Xh[(size_t)T_SEQ * D_MODEL];   // x rounded to fp16
__device__ __half g_Wqkv[(size_t)NQKV * D_MODEL];  // [WQ^T;WK^T;WV^T] [n][k] fp16
__device__ __half g_WOt[(size_t)D_MODEL * D_MODEL];// WO^T [n][k] fp16

// ---------------------------------------------------------------------------
// Helpers (sm_80-era PTX: mma.sync, ldmatrix, cp.async, shfl)
// ---------------------------------------------------------------------------
__device__ __forceinline__ uint32_t smem_to_u32(const void* p) {
    uint32_t a;
    asm("{ .reg .u64 t; cvta.to.shared.u64 t, %1; cvt.u32.u64 %0, t; }"
        : "=r"(a) : "l"(p));
    return a;
}

__device__ __forceinline__ void cp_async16(uint32_t saddr, const void* g) {
    asm volatile("cp.async.cg.shared.global [%0], [%1], 16;" :: "r"(saddr), "l"(g));
}
#define CP_COMMIT() asm volatile("cp.async.commit_group;" ::: "memory")
#define CP_WAIT_0() asm volatile("cp.async.wait_group 0;" ::: "memory")
#define CP_WAIT_1() asm volatile("cp.async.wait_group 1;" ::: "memory")

// fp16: D += A(16x16) * B(16x8), fp32 accumulate
__device__ __forceinline__ void mma_f16(float* d, const uint32_t* a, const uint32_t* b) {
    asm volatile(
        "mma.sync.aligned.m16n8k16.row.col.f32.f16.f16.f32 "
        "{%0,%1,%2,%3}, {%4,%5,%6,%7}, {%8,%9}, {%0,%1,%2,%3};"
        : "+f"(d[0]), "+f"(d[1]), "+f"(d[2]), "+f"(d[3])
        : "r"(a[0]), "r"(a[1]), "r"(a[2]), "r"(a[3]), "r"(b[0]), "r"(b[1]));
}

__device__ __forceinline__ void ldsm_x4(uint32_t& r0, uint32_t& r1,
                                        uint32_t& r2, uint32_t& r3, uint32_t addr) {
    asm volatile("ldmatrix.sync.aligned.m8n8.x4.shared.b16 {%0,%1,%2,%3}, [%4];"
                 : "=r"(r0), "=r"(r1), "=r"(r2), "=r"(r3) : "r"(addr));
}

// ---------------------------------------------------------------------------
// GEMM (fp16 mma.sync m16n8k16 + ldmatrix): C[M,N] = A[M,K] @ Bt[N,K]^T
//   128x128 tile, 256 thr, warp grid 2m x 4n, K-tile 32, 3-stage cp.async,
//   2 CTAs/SM.  cmode 0: fp32 row-major C.  cmode 3: QKV epilogue + RoPE.
// ---------------------------------------------------------------------------
#define GM_KT 32
#define GM_ROW 40                         // fp16 per smem row (32 data + 8 pad)
#define GM_STG 3
#define GM_STAGE_B (128 * GM_ROW * 2)     // 10,240 B
#define GM_SMEM (GM_STG * GM_STAGE_B * 2) // 61,440 B

__device__ __forceinline__ void gm_load_stage(
    const __half* __restrict__ A, const __half* __restrict__ Bt,
    uint32_t sA, uint32_t sB, int kt, int K, int tid)
{
    #pragma unroll
    for (int it = 0; it < 2; it++) {
        int idx = it * 256 + tid;
        int row = idx >> 2;
        int c   = idx & 3;
        uint32_t off = (uint32_t)(row * GM_ROW * 2 + c * 16);
        cp_async16(sA + off, A  + (size_t)row * K + kt * GM_KT + c * 8);
        cp_async16(sB + off, Bt + (size_t)row * K + kt * GM_KT + c * 8);
    }
}

__global__ __launch_bounds__(256, 2)
void gemm_mma(const __half* __restrict__ A, const __half* __restrict__ Bt,
              float* __restrict__ C, int M, int N, int K, int cmode)
{
    extern __shared__ __align__(16) char gsmc[];
    const uint32_t sAu = smem_to_u32(gsmc);
    const uint32_t sBu = sAu + GM_STG * GM_STAGE_B;

    const int tid  = threadIdx.x;
    const int w    = tid >> 5;
    const int lane = tid & 31;
    const int g    = lane >> 2;
    const int qd   = lane & 3;
    const int lr   = lane & 7;
    const int wm   = w & 1;
    const int wn   = w >> 1;
    const int m0   = blockIdx.y * 128;
    const int n0   = blockIdx.x * 128;
    const int NKT  = K / GM_KT;

    const __half* Ab = A  + (size_t)m0 * K;
    const __half* Bb = Bt + (size_t)n0 * K;

    const uint32_t aSel = ((lane >> 3) & 1);
    const uint32_t aCol = ((lane >> 4) & 1);
    const uint32_t bSel = ((lane >> 4) & 1);
    const uint32_t bCol = ((lane >> 3) & 1);

    const uint32_t aOffL = (uint32_t)((aSel * 8 + lr) + 64 * wm) * (GM_ROW * 2) + aCol * 16;
    const uint32_t bOffL = (uint32_t)((bSel * 8 + lr) + 32 * wn) * (GM_ROW * 2) + bCol * 16;

    float acc[4][4][4];
    #pragma unroll
    for (int mt = 0; mt < 4; mt++)
        #pragma unroll
        for (int nt = 0; nt < 4; nt++)
            #pragma unroll
            for (int e = 0; e < 4; e++) acc[mt][nt][e] = 0.f;

    gm_load_stage(Ab, Bb, sAu, sBu, 0, K, tid); CP_COMMIT();
    gm_load_stage(Ab, Bb, sAu + GM_STAGE_B, sBu + GM_STAGE_B, 1, K, tid); CP_COMMIT();

    for (int kt = 0; kt < NKT; kt++) {
        CP_WAIT_1();
        __syncthreads();
        if (kt + 2 < NKT) {
            int s2 = (kt + 2) % GM_STG;
            gm_load_stage(Ab, Bb, sAu + s2 * GM_STAGE_B, sBu + s2 * GM_STAGE_B,
                          kt + 2, K, tid);
            CP_COMMIT();
        }
        uint32_t sa = sAu + (kt % GM_STG) * GM_STAGE_B + aOffL;
        uint32_t sb = sBu + (kt % GM_STG) * GM_STAGE_B + bOffL;

        #pragma unroll
        for (int ks = 0; ks < 2; ks++) {
            uint32_t a[4][4];
            #pragma unroll
            for (int mt = 0; mt < 4; mt++)
                ldsm_x4(a[mt][0], a[mt][1], a[mt][2], a[mt][3],
                        sa + (uint32_t)(16 * mt * GM_ROW * 2) + ks * 32);
            uint32_t b[4][2];
            #pragma unroll
            for (int ntp = 0; ntp < 2; ntp++) {
                uint32_t t0, t1, t2, t3;
                ldsm_x4(t0, t1, t2, t3,
                        sb + (uint32_t)(16 * ntp * GM_ROW * 2) + ks * 32);
                b[2*ntp][0] = t0; b[2*ntp][1] = t1;
                b[2*ntp+1][0] = t2; b[2*ntp+1][1] = t3;
            }
            #pragma unroll
            for (int mt = 0; mt < 4; mt++)
                #pragma unroll
                for (int nt = 0; nt < 4; nt++)
                    mma_f16(acc[mt][nt], a[mt], b[nt]);
        }
    }

    // epilogue
    #pragma unroll
    for (int mt = 0; mt < 4; mt++) {
        #pragma unroll
        for (int nt = 0; nt < 4; nt++) {
            int r = m0 + 64 * wm + 16 * mt + g;
            int c = n0 + 32 * wn + 8 * nt + 2 * qd;
            if (cmode == 0) {
                #pragma unroll
                for (int hf = 0; hf < 2; hf++) {
                    int rr = r + hf * 8;
                    *(float2*)&C[(size_t)rr * N + c] =
                        make_float2(acc[mt][nt][2*hf], acc[mt][nt][2*hf+1]);
                }
            } else if (c < D_MODEL) {
                // Q + RoPE, pre-scaled by QSCALE -> g_Q[h][t][d] fp16
                int i = (c & 127) >> 1;
                float omega = (float)(1.0 / pow(10000.0, (double)(2 * i) / (double)DH));
                #pragma unroll
                for (int hf = 0; hf < 2; hf++) {
                    int rr = r + hf * 8;
                    float s, co;
                    sincosf((float)rr * omega, &s, &co);
                    float v0 = acc[mt][nt][2*hf], v1 = acc[mt][nt][2*hf+1];
                    size_t base = ((size_t)(c >> 7) * T_SEQ + rr) * 128 + (c & 127);
                    *(__half2*)&g_Q[base] =
                        __floats2half2_rn((v0 * co - v1 * s) * QSCALE,
                                          (v0 * s + v1 * co) * QSCALE);
                }
            } else if (c < D_MODEL + DKV) {
                // K + RoPE -> g_K[kh][t][d] fp16
                int d  = c - D_MODEL;
                int kh = d >> 7;
                int dd = d & 127;
                int i  = dd >> 1;
                float omega = (float)(1.0 / pow(10000.0, (double)(2 * i) / (double)DH));
                #pragma unroll
                for (int hf = 0; hf < 2; hf++) {
                    int rr = r + hf * 8;
                    float s, co;
                    sincosf((float)rr * omega, &s, &co);
                    float v0 = acc[mt][nt][2*hf], v1 = acc[mt][nt][2*hf+1];
                    size_t base = ((size_t)kh * T_SEQ + rr) * 128 + dd;
                    *(__half2*)&g_K[base] =
                        __floats2half2_rn(v0 * co - v1 * s, v0 * s + v1 * co);
                }
            } else {
                // V -> g_V[kh][d][t] fp16 (d-major)
                int d  = c - (D_MODEL + DKV);
                int kh = d >> 7;
                int dd = d & 127;
                #pragma unroll
                for (int hf = 0; hf < 2; hf++) {
                    int rr = r + hf * 8;
                    size_t base = ((size_t)kh * DH + dd) * T_SEQ + rr;
                    g_V[base]         = __float2half_rn(acc[mt][nt][2*hf]);
                    g_V[base + T_SEQ] = __float2half_rn(acc[mt][nt][2*hf+1]);
                }
            }
        }
    }
}

// ---------------------------------------------------------------------------
// Batched weight transpose + fp16 rounding
// ---------------------------------------------------------------------------
__global__ void transpose_rnd4(const float* __restrict__ WQ, const float* __restrict__ WK,
                               const float* __restrict__ WV, const float* __restrict__ WO)
{
    __shared__ float t[32][33];
    int z = blockIdx.z;
    const float* src;
    __half* dst;
    int N;
    if (z == 0)      { src = WQ; dst = g_Wqkv;                              N = D_MODEL; }
    else if (z == 1) { src = WK; dst = g_Wqkv + (size_t)D_MODEL * D_MODEL;  N = DKV; }
    else if (z == 2) { src = WV; dst = g_Wqkv + (size_t)(D_MODEL + DKV) * D_MODEL; N = DKV; }
    else             { src = WO; dst = g_WOt;                               N = D_MODEL; }

    int n0 = blockIdx.x * 32;
    if (n0 >= N) return;
    int k0 = blockIdx.y * 32;
    #pragma unroll
    for (int i = threadIdx.y; i < 32; i += 8)
        t[i][threadIdx.x] = src[(size_t)(k0 + i) * N + n0 + threadIdx.x];
    __syncthreads();
    #pragma unroll
    for (int i = threadIdx.y; i < 32; i += 8)
        dst[(size_t)(n0 + i) * D_MODEL + k0 + threadIdx.x] =
            __float2half_rn(t[threadIdx.x][i]);
}

__global__ void round_fp16_kernel(const float4* __restrict__ in, __half2* __restrict__ out, int n4)
{
    int i = blockIdx.x * blockDim.x + threadIdx.x;
    if (i < n4) {
        float4 v = in[i];
        out[2*i]     = __floats2half2_rn(v.x, v.y);
        out[2*i + 1] = __floats2half2_rn(v.z, v.w);
    }
}

// ---------------------------------------------------------------------------
// Flash attention, fp16 mma.sync, kv-tile 128 (halved softmax/barrier passes),
// exp2 softmax (Q pre-scaled by 1/sqrt(d)*log2e).
// q-tile 128, 256 thr (8 warps), warp owns 16 q-rows.
// Smem: Q[128x272B] | K[2][128x272B] | V[2][128x272B] | P[128x272B] = 204 KB.
// ---------------------------------------------------------------------------
#define FROW_B 272                    // 128 fp16 + 8 pad (row stride everywhere)
#define FBUF_B (128 * FROW_B)         // 34,816 B
#define QS_OFF 0
#define KS_OFF FBUF_B
#define VS_OFF (KS_OFF + 2 * FBUF_B)
#define PS_OFF (VS_OFF + 2 * FBUF_B)
#define FL_SMEM (PS_OFF + FBUF_B)     // 208,896 B

__device__ __forceinline__ void fl_load_tile_td(
    const __half* __restrict__ src, uint32_t dst, size_t row_stride, int row0, int tid)
{
    #pragma unroll
    for (int it = 0; it < 8; it++) {       // 128 rows x 256B
        int idx = it * 256 + tid;
        int r = idx >> 4, c = idx & 15;
        cp_async16(dst + (uint32_t)(r * FROW_B + c * 16),
                   src + (size_t)(row0 + r) * row_stride + c * 8);
    }
}

__device__ __forceinline__ void fl_load_v(
    const __half* __restrict__ Vh, uint32_t dst, int kbase, int tid)
{
    #pragma unroll
    for (int it = 0; it < 8; it++) {       // 128 d-rows x 128 t fp16
        int idx = it * 256 + tid;
        int r = idx >> 4, c = idx & 15;
        cp_async16(dst + (uint32_t)(r * FROW_B + c * 16),
                   Vh + (size_t)r * T_SEQ + kbase + c * 8);
    }
}

__global__ __launch_bounds__(256, 1)
void flash_mma(const __half* __restrict__ Qg, const __half* __restrict__ Kg,
               const __half* __restrict__ Vg, __half* __restrict__ Ctx)
{
    extern __shared__ __align__(16) char smc[];
    __half* Ps = (__half*)(smc + PS_OFF);

    const int tid  = threadIdx.x;
    const int w    = tid >> 5;
    const int lane = tid & 31;
    const int g    = lane >> 2;
    const int qd   = lane & 3;
    const int qt   = gridDim.x - 1 - blockIdx.x;   // big tiles first
    const int h    = blockIdx.y;
    const int kh   = h >> 2;
    const int qbase = qt * 128;
    const int r0   = 16 * w + g;

    const __half* Qh = Qg + (size_t)h * T_SEQ * DH;
    const __half* Kh = Kg + (size_t)kh * T_SEQ * DH;   // [t][d]
    const __half* Vh = Vg + (size_t)kh * DH * T_SEQ;   // [d][t]

    const uint32_t smu = smem_to_u32(smc);
    const uint32_t qsu = smu + QS_OFF;
    const uint32_t ksu = smu + KS_OFF;
    const uint32_t vsu = smu + VS_OFF;
    const uint32_t psu = smu + PS_OFF;

    // ldmatrix lane selectors
    const uint32_t aSel = ((lane >> 3) & 1);
    const uint32_t aCol = ((lane >> 4) & 1);
    const uint32_t bSel = ((lane >> 4) & 1);
    const uint32_t bCol = ((lane >> 3) & 1);
    const int      lr   = lane & 7;

    const uint32_t qOffL = (uint32_t)(16 * w + aSel * 8 + lr) * FROW_B + aCol * 16;
    const uint32_t kOffL = (uint32_t)(bSel * 8 + lr) * FROW_B + bCol * 16;
    const uint32_t vOffL = (uint32_t)(bSel * 8 + lr) * FROW_B + bCol * 16;
    const uint32_t pOffL = (uint32_t)(16 * w + aSel * 8 + lr) * FROW_B + aCol * 16;

    const int ntiles = qt + 1;

    // prologue: Q tile + K(0) + V(0), one commit group
    fl_load_tile_td(Qh, qsu, DH, qbase, tid);
    fl_load_tile_td(Kh, ksu, DH, 0, tid);
    fl_load_v(Vh, vsu, 0, tid);
    CP_COMMIT();

    float m_i[2] = {-1e30f, -1e30f};
    float l_i[2] = {0.f, 0.f};
    float o[16][4];
    #pragma unroll
    for (int nt = 0; nt < 16; nt++)
        #pragma unroll
        for (int e = 0; e < 4; e++) o[nt][e] = 0.f;

    for (int jt = 0; jt < ntiles; jt++) {
        CP_WAIT_0();
        __syncthreads();

        if (jt + 1 < ntiles) {
            uint32_t kdst = ksu + ((jt + 1) & 1) * FBUF_B;
            uint32_t vdst = vsu + ((jt + 1) & 1) * FBUF_B;
            fl_load_tile_td(Kh, kdst, DH, (jt + 1) * 128, tid);
            fl_load_v(Vh, vdst, (jt + 1) * 128, tid);
            CP_COMMIT();
        }

        const int kbase = jt * 128;
        const uint32_t kb = ksu + (jt & 1) * FBUF_B + kOffL;
        const uint32_t vb = vsu + (jt & 1) * FBUF_B + vOffL;

        // S = Q @ K^T  (16 n-tiles of 8 kv cols; Q frags reloaded per tile)
        float s[16][4];
        #pragma unroll
        for (int nt = 0; nt < 16; nt++)
            #pragma unroll
            for (int e = 0; e < 4; e++) s[nt][e] = 0.f;

        #pragma unroll
        for (int kk = 0; kk < 8; kk++) {
            uint32_t qf[4];
            ldsm_x4(qf[0], qf[1], qf[2], qf[3], qsu + qOffL + kk * 32);
            #pragma unroll
            for (int ntp = 0; ntp < 8; ntp++) {
                uint32_t b0, b1, b2, b3;
                ldsm_x4(b0, b1, b2, b3,
                        kb + (uint32_t)(ntp * 16 * FROW_B) + kk * 32);
                uint32_t bb0[2] = {b0, b1};
                uint32_t bb1[2] = {b2, b3};
                mma_f16(s[2*ntp],     qf, bb0);
                mma_f16(s[2*ntp + 1], qf, bb1);
            }
        }

        if (jt == qt) {   // diagonal tile: mask col > row (log2-domain logits)
            #pragma unroll
            for (int nt = 0; nt < 16; nt++)
                #pragma unroll
                for (int e = 0; e < 4; e++) {
                    int col = kbase + nt * 8 + 2 * qd + (e & 1);
                    int row = qbase + r0 + ((e >> 1) << 3);
                    if (col > row) s[nt][e] = -1e30f;
                }
        }

        // online softmax in log2 domain — quad shfl reduce
        float mx0 = -1e30f, mx1 = -1e30f;
        #pragma unroll
        for (int nt = 0; nt < 16; nt++) {
            mx0 = fmaxf(mx0, fmaxf(s[nt][0], s[nt][1]));
            mx1 = fmaxf(mx1, fmaxf(s[nt][2], s[nt][3]));
        }
        mx0 = fmaxf(mx0, __shfl_xor_sync(0xffffffffu, mx0, 1));
        mx0 = fmaxf(mx0, __shfl_xor_sync(0xffffffffu, mx0, 2));
        mx1 = fmaxf(mx1, __shfl_xor_sync(0xffffffffu, mx1, 1));
        mx1 = fmaxf(mx1, __shfl_xor_sync(0xffffffffu, mx1, 2));
        float mn0 = fmaxf(m_i[0], mx0);
        float mn1 = fmaxf(m_i[1], mx1);
        float sc0 = exp2f(m_i[0] - mn0);
        float sc1 = exp2f(m_i[1] - mn1);
        m_i[0] = mn0; m_i[1] = mn1;

        float rs0 = 0.f, rs1 = 0.f;
        #pragma unroll
        for (int nt = 0; nt < 16; nt++) {
            s[nt][0] = exp2f(s[nt][0] - mn0);
            s[nt][1] = exp2f(s[nt][1] - mn0);
            s[nt][2] = exp2f(s[nt][2] - mn1);
            s[nt][3] = exp2f(s[nt][3] - mn1);
            rs0 += s[nt][0] + s[nt][1];
            rs1 += s[nt][2] + s[nt][3];
        }
        rs0 += __shfl_xor_sync(0xffffffffu, rs0, 1);
        rs0 += __shfl_xor_sync(0xffffffffu, rs0, 2);
        rs1 += __shfl_xor_sync(0xffffffffu, rs1, 1);
        rs1 += __shfl_xor_sync(0xffffffffu, rs1, 2);
        l_i[0] = l_i[0] * sc0 + rs0;
        l_i[1] = l_i[1] * sc1 + rs1;

        #pragma unroll
        for (int nt = 0; nt < 16; nt++) {
            o[nt][0] *= sc0; o[nt][1] *= sc0;
            o[nt][2] *= sc1; o[nt][3] *= sc1;
        }
        // stage P as fp16 — warp-private rows
        #pragma unroll
        for (int nt = 0; nt < 16; nt++) {
            *(__half2*)&Ps[(r0    ) * (FROW_B/2) + nt * 8 + 2 * qd] =
                __floats2half2_rn(s[nt][0], s[nt][1]);
            *(__half2*)&Ps[(r0 + 8) * (FROW_B/2) + nt * 8 + 2 * qd] =
                __floats2half2_rn(s[nt][2], s[nt][3]);
        }
        __syncwarp();

        // O += P @ V   (8 x k16 over kv=128, 8 d-groups of 16)
        #pragma unroll
        for (int kk = 0; kk < 8; kk++) {
            uint32_t a[4];
            ldsm_x4(a[0], a[1], a[2], a[3], psu + pOffL + kk * 32);
            #pragma unroll
            for (int dg = 0; dg < 8; dg++) {
                uint32_t b0, b1, b2, b3;
                ldsm_x4(b0, b1, b2, b3,
                        vb + (uint32_t)(dg * 16 * FROW_B) + kk * 32);
                uint32_t bb0[2] = {b0, b1};
                uint32_t bb1[2] = {b2, b3};
                mma_f16(o[2*dg],     a, bb0);
                mma_f16(o[2*dg + 1], a, bb1);
            }
        }
    }

    // epilogue: normalize, write ctx as fp16
    float inv0 = 1.0f / l_i[0];
    float inv1 = 1.0f / l_i[1];
    #pragma unroll
    for (int nt = 0; nt < 16; nt++) {
        size_t b0 = (size_t)(qbase + r0    ) * D_MODEL + h * DH + nt * 8 + 2 * qd;
        size_t b1 = (size_t)(qbase + r0 + 8) * D_MODEL + h * DH + nt * 8 + 2 * qd;
        *(__half2*)&Ctx[b0] = __floats2half2_rn(o[nt][0] * inv0, o[nt][1] * inv0);
        *(__half2*)&Ctx[b1] = __floats2half2_rn(o[nt][2] * inv1, o[nt][3] * inv1);
    }
}

// ---------------------------------------------------------------------------
// kernel_launch
// ---------------------------------------------------------------------------
extern "C" void kernel_launch(void* const* d_in, const int* in_sizes, int n_in,
                              void* d_out, int out_size)
{
    const float* x  = (const float*)d_in[0];
    const float* WQ = (const float*)d_in[1];
    const float* WK = (const float*)d_in[2];
    const float* WV = (const float*)d_in[3];
    const float* WO = (const float*)d_in[4];
    float* out = (float*)d_out;

    __half *qp, *kp, *vp, *cp, *xh, *wqkv, *wot;
    cudaGetSymbolAddress((void**)&qp,   g_Q);
    cudaGetSymbolAddress((void**)&kp,   g_K);
    cudaGetSymbolAddress((void**)&vp,   g_V);
    cudaGetSymbolAddress((void**)&cp,   g_C);
    cudaGetSymbolAddress((void**)&xh,   g_Xh);
    cudaGetSymbolAddress((void**)&wqkv, g_Wqkv);
    cudaGetSymbolAddress((void**)&wot,  g_WOt);

    cudaFuncSetAttribute(flash_mma,
                         cudaFuncAttributeMaxDynamicSharedMemorySize, FL_SMEM);
    cudaFuncSetAttribute(gemm_mma,
                         cudaFuncAttributeMaxDynamicSharedMemorySize, GM_SMEM);

    // 1) round x to fp16
    {
        int n4 = T_SEQ * D_MODEL / 4;
        round_fp16_kernel<<<(n4 + 255) / 256, 256>>>((const float4*)x, (__half2*)xh, n4);
    }
    // 2) all weight transposes (fp16) in one launch
    transpose_rnd4<<<dim3(64, 64, 4), dim3(32, 8)>>>(WQ, WK, WV, WO);

    // 3) fused QKV projection (fp16 MMA; epilogue: RoPE + Q pre-scale)
    gemm_mma<<<dim3(NQKV/128, T_SEQ/128), 256, GM_SMEM>>>(xh, wqkv, nullptr,
                                                          T_SEQ, NQKV, D_MODEL, 3);

    // 4) attention (fp16 tensor cores, kv-tile 128, exp2 softmax)
    flash_mma<<<dim3(T_SEQ/128, NH), 256, FL_SMEM>>>(qp, kp, vp, cp);

    // 5) output projection (fp16 MMA, fp32 out)
    gemm_mma<<<dim3(D_MODEL/128, T_SEQ/128), 256, GM_SMEM>>>(cp, wot, out,
                                                             T_SEQ, D_MODEL, D_MODEL, 0);
}

// round 17
// speedup vs baseline: 1.9816x; 1.0800x over previous
#include <cuda_runtime.h>
#include <cuda_fp16.h>
#include <math.h>
#include <stdint.h>

// Problem constants
#define T_SEQ 4096
#define D_MODEL 2048
#define DH 128
#define NH 16
#define NKV 4
#define DKV 512   // NKV * DH
#define NQKV 3072 // D_MODEL + 2*DKV

// Q pre-scale: (1/sqrt(128)) * log2(e)  — folded so flash uses exp2f
#define QSCALE 0.12751743560f

// ---------------------------------------------------------------------------
// Scratch (device globals — no allocations allowed)
// ---------------------------------------------------------------------------
__device__ __half g_Q[(size_t)NH * T_SEQ * DH];    // [h][t][d]  roped, pre-scaled fp16
__device__ __half g_K[(size_t)NKV * T_SEQ * DH];   // [kh][t][d] roped fp16
__device__ __half g_V[(size_t)NKV * DH * T_SEQ];   // [kh][d][t] fp16
__device__ __half g_C[(size_t)T_SEQ * D_MODEL];    // ctx [t][h*128+d] fp16
__device__ __half g_Xh[(size_t)T_SEQ * D_MODEL];   // x rounded to fp16
__device__ __half g_Wqkv[(size_t)NQKV * D_MODEL];  // [WQ^T;WK^T;WV^T] [n][k] fp16
__device__ __half g_WOt[(size_t)D_MODEL * D_MODEL];// WO^T [n][k] fp16
__device__ float  g_omega[DH / 2];                 // RoPE omega table (fp32)

// ---------------------------------------------------------------------------
// Helpers (sm_80-era PTX: mma.sync, ldmatrix, cp.async, shfl)
// ---------------------------------------------------------------------------
__device__ __forceinline__ uint32_t smem_to_u32(const void* p) {
    uint32_t a;
    asm("{ .reg .u64 t; cvta.to.shared.u64 t, %1; cvt.u32.u64 %0, t; }"
        : "=r"(a) : "l"(p));
    return a;
}

__device__ __forceinline__ void cp_async16(uint32_t saddr, const void* g) {
    asm volatile("cp.async.cg.shared.global [%0], [%1], 16;" :: "r"(saddr), "l"(g));
}
#define CP_COMMIT() asm volatile("cp.async.commit_group;" ::: "memory")
#define CP_WAIT_0() asm volatile("cp.async.wait_group 0;" ::: "memory")
#define CP_WAIT_1() asm volatile("cp.async.wait_group 1;" ::: "memory")

// fp16: D += A(16x16) * B(16x8), fp32 accumulate
__device__ __forceinline__ void mma_f16(float* d, const uint32_t* a, const uint32_t* b) {
    asm volatile(
        "mma.sync.aligned.m16n8k16.row.col.f32.f16.f16.f32 "
        "{%0,%1,%2,%3}, {%4,%5,%6,%7}, {%8,%9}, {%0,%1,%2,%3};"
        : "+f"(d[0]), "+f"(d[1]), "+f"(d[2]), "+f"(d[3])
        : "r"(a[0]), "r"(a[1]), "r"(a[2]), "r"(a[3]), "r"(b[0]), "r"(b[1]));
}

__device__ __forceinline__ void ldsm_x4(uint32_t& r0, uint32_t& r1,
                                        uint32_t& r2, uint32_t& r3, uint32_t addr) {
    asm volatile("ldmatrix.sync.aligned.m8n8.x4.shared.b16 {%0,%1,%2,%3}, [%4];"
                 : "=r"(r0), "=r"(r1), "=r"(r2), "=r"(r3) : "r"(addr));
}

// ---------------------------------------------------------------------------
// GEMM (fp16 mma.sync m16n8k16 + ldmatrix): C[M,N] = A[M,K] @ Bt[N,K]^T
//   128x128 tile, 256 thr, warp grid 2m x 4n, K-tile 64, 3-stage cp.async,
//   2 CTAs/SM (216 KB smem/SM).
//   cmode 0: fp32 row-major C.  cmode 3: QKV epilogue + RoPE (omega table).
// ---------------------------------------------------------------------------
#define GM_KT 64
#define GM_ROW 72                         // fp16 per smem row (64 data + 8 pad)
#define GM_ROW_B 144                      // bytes per row
#define GM_STG 3
#define GM_STAGE_B (128 * GM_ROW_B)       // one matrix: 18,432 B
#define GM_SMEM (GM_STG * GM_STAGE_B * 2) // 110,592 B

__device__ __forceinline__ void gm_load_stage(
    const __half* __restrict__ A, const __half* __restrict__ Bt,
    uint32_t sA, uint32_t sB, int kt, int K, int tid)
{
    #pragma unroll
    for (int it = 0; it < 4; it++) {
        int idx = it * 256 + tid;
        int row = idx >> 3;               // 0..127
        int c   = idx & 7;                // 16B chunk (8 fp16)
        uint32_t off = (uint32_t)(row * GM_ROW_B + c * 16);
        cp_async16(sA + off, A  + (size_t)row * K + kt * GM_KT + c * 8);
        cp_async16(sB + off, Bt + (size_t)row * K + kt * GM_KT + c * 8);
    }
}

__global__ __launch_bounds__(256, 2)
void gemm_mma(const __half* __restrict__ A, const __half* __restrict__ Bt,
              float* __restrict__ C, int M, int N, int K, int cmode)
{
    extern __shared__ __align__(16) char gsmc[];
    const uint32_t sAu = smem_to_u32(gsmc);
    const uint32_t sBu = sAu + GM_STG * GM_STAGE_B;

    const int tid  = threadIdx.x;
    const int w    = tid >> 5;
    const int lane = tid & 31;
    const int g    = lane >> 2;
    const int qd   = lane & 3;
    const int lr   = lane & 7;
    const int wm   = w & 1;
    const int wn   = w >> 1;
    const int m0   = blockIdx.y * 128;
    const int n0   = blockIdx.x * 128;
    const int NKT  = K / GM_KT;

    const __half* Ab = A  + (size_t)m0 * K;
    const __half* Bb = Bt + (size_t)n0 * K;

    const uint32_t aSel = ((lane >> 3) & 1);
    const uint32_t aCol = ((lane >> 4) & 1);
    const uint32_t bSel = ((lane >> 4) & 1);
    const uint32_t bCol = ((lane >> 3) & 1);

    const uint32_t aOffL = (uint32_t)((aSel * 8 + lr) + 64 * wm) * GM_ROW_B + aCol * 16;
    const uint32_t bOffL = (uint32_t)((bSel * 8 + lr) + 32 * wn) * GM_ROW_B + bCol * 16;

    float acc[4][4][4];
    #pragma unroll
    for (int mt = 0; mt < 4; mt++)
        #pragma unroll
        for (int nt = 0; nt < 4; nt++)
            #pragma unroll
            for (int e = 0; e < 4; e++) acc[mt][nt][e] = 0.f;

    gm_load_stage(Ab, Bb, sAu, sBu, 0, K, tid); CP_COMMIT();
    gm_load_stage(Ab, Bb, sAu + GM_STAGE_B, sBu + GM_STAGE_B, 1, K, tid); CP_COMMIT();

    for (int kt = 0; kt < NKT; kt++) {
        CP_WAIT_1();
        __syncthreads();
        if (kt + 2 < NKT) {
            int s2 = (kt + 2) % GM_STG;
            gm_load_stage(Ab, Bb, sAu + s2 * GM_STAGE_B, sBu + s2 * GM_STAGE_B,
                          kt + 2, K, tid);
            CP_COMMIT();
        }
        uint32_t sa = sAu + (kt % GM_STG) * GM_STAGE_B + aOffL;
        uint32_t sb = sBu + (kt % GM_STG) * GM_STAGE_B + bOffL;

        #pragma unroll
        for (int ks = 0; ks < 4; ks++) {      // four k16 steps per K-tile
            uint32_t a[4][4];
            #pragma unroll
            for (int mt = 0; mt < 4; mt++)
                ldsm_x4(a[mt][0], a[mt][1], a[mt][2], a[mt][3],
                        sa + (uint32_t)(16 * mt * GM_ROW_B) + ks * 32);
            uint32_t b[4][2];
            #pragma unroll
            for (int ntp = 0; ntp < 2; ntp++) {
                uint32_t t0, t1, t2, t3;
                ldsm_x4(t0, t1, t2, t3,
                        sb + (uint32_t)(16 * ntp * GM_ROW_B) + ks * 32);
                b[2*ntp][0] = t0; b[2*ntp][1] = t1;
                b[2*ntp+1][0] = t2; b[2*ntp+1][1] = t3;
            }
            #pragma unroll
            for (int mt = 0; mt < 4; mt++)
                #pragma unroll
                for (int nt = 0; nt < 4; nt++)
                    mma_f16(acc[mt][nt], a[mt], b[nt]);
        }
    }

    // epilogue
    #pragma unroll
    for (int mt = 0; mt < 4; mt++) {
        #pragma unroll
        for (int nt = 0; nt < 4; nt++) {
            int r = m0 + 64 * wm + 16 * mt + g;
            int c = n0 + 32 * wn + 8 * nt + 2 * qd;
            if (cmode == 0) {
                #pragma unroll
                for (int hf = 0; hf < 2; hf++) {
                    int rr = r + hf * 8;
                    *(float2*)&C[(size_t)rr * N + c] =
                        make_float2(acc[mt][nt][2*hf], acc[mt][nt][2*hf+1]);
                }
            } else if (c < D_MODEL) {
                // Q + RoPE (omega table), pre-scaled -> g_Q[h][t][d] fp16
                int i = (c & 127) >> 1;
                float omega = g_omega[i];
                #pragma unroll
                for (int hf = 0; hf < 2; hf++) {
                    int rr = r + hf * 8;
                    float s, co;
                    sincosf((float)rr * omega, &s, &co);
                    float v0 = acc[mt][nt][2*hf], v1 = acc[mt][nt][2*hf+1];
                    size_t base = ((size_t)(c >> 7) * T_SEQ + rr) * 128 + (c & 127);
                    *(__half2*)&g_Q[base] =
                        __floats2half2_rn((v0 * co - v1 * s) * QSCALE,
                                          (v0 * s + v1 * co) * QSCALE);
                }
            } else if (c < D_MODEL + DKV) {
                // K + RoPE (omega table) -> g_K[kh][t][d] fp16
                int d  = c - D_MODEL;
                int kh = d >> 7;
                int dd = d & 127;
                float omega = g_omega[dd >> 1];
                #pragma unroll
                for (int hf = 0; hf < 2; hf++) {
                    int rr = r + hf * 8;
                    float s, co;
                    sincosf((float)rr * omega, &s, &co);
                    float v0 = acc[mt][nt][2*hf], v1 = acc[mt][nt][2*hf+1];
                    size_t base = ((size_t)kh * T_SEQ + rr) * 128 + dd;
                    *(__half2*)&g_K[base] =
                        __floats2half2_rn(v0 * co - v1 * s, v0 * s + v1 * co);
                }
            } else {
                // V -> g_V[kh][d][t] fp16 (d-major)
                int d  = c - (D_MODEL + DKV);
                int kh = d >> 7;
                int dd = d & 127;
                #pragma unroll
                for (int hf = 0; hf < 2; hf++) {
                    int rr = r + hf * 8;
                    size_t base = ((size_t)kh * DH + dd) * T_SEQ + rr;
                    g_V[base]         = __float2half_rn(acc[mt][nt][2*hf]);
                    g_V[base + T_SEQ] = __float2half_rn(acc[mt][nt][2*hf+1]);
                }
            }
        }
    }
}

// ---------------------------------------------------------------------------
// Batched weight transpose + fp16 rounding
// ---------------------------------------------------------------------------
__global__ void transpose_rnd4(const float* __restrict__ WQ, const float* __restrict__ WK,
                               const float* __restrict__ WV, const float* __restrict__ WO)
{
    __shared__ float t[32][33];
    int z = blockIdx.z;
    const float* src;
    __half* dst;
    int N;
    if (z == 0)      { src = WQ; dst = g_Wqkv;                              N = D_MODEL; }
    else if (z == 1) { src = WK; dst = g_Wqkv + (size_t)D_MODEL * D_MODEL;  N = DKV; }
    else if (z == 2) { src = WV; dst = g_Wqkv + (size_t)(D_MODEL + DKV) * D_MODEL; N = DKV; }
    else             { src = WO; dst = g_WOt;                               N = D_MODEL; }

    int n0 = blockIdx.x * 32;
    if (n0 >= N) return;
    int k0 = blockIdx.y * 32;
    #pragma unroll
    for (int i = threadIdx.y; i < 32; i += 8)
        t[i][threadIdx.x] = src[(size_t)(k0 + i) * N + n0 + threadIdx.x];
    __syncthreads();
    #pragma unroll
    for (int i = threadIdx.y; i < 32; i += 8)
        dst[(size_t)(n0 + i) * D_MODEL + k0 + threadIdx.x] =
            __float2half_rn(t[threadIdx.x][i]);
}

// x fp32 -> fp16; block 0 also fills the RoPE omega table (identical bits
// to the previous per-thread double-pow computation).
__global__ void round_fp16_kernel(const float4* __restrict__ in, __half2* __restrict__ out, int n4)
{
    if (blockIdx.x == 0 && threadIdx.x < DH / 2) {
        int i = threadIdx.x;
        g_omega[i] = (float)(1.0 / pow(10000.0, (double)(2 * i) / (double)DH));
    }
    int i = blockIdx.x * blockDim.x + threadIdx.x;
    if (i < n4) {
        float4 v = in[i];
        out[2*i]     = __floats2half2_rn(v.x, v.y);
        out[2*i + 1] = __floats2half2_rn(v.z, v.w);
    }
}

// ---------------------------------------------------------------------------
// Flash attention, fp16 mma.sync, kv-tile 128, exp2 softmax (Q pre-scaled).
// q-tile 128, 256 thr (8 warps), warp owns 16 q-rows. (unchanged — RF-bound)
// Smem: Q[128x272B] | K[2][128x272B] | V[2][128x272B] | P[128x272B] = 204 KB.
// ---------------------------------------------------------------------------
#define FROW_B 272
#define FBUF_B (128 * FROW_B)
#define QS_OFF 0
#define KS_OFF FBUF_B
#define VS_OFF (KS_OFF + 2 * FBUF_B)
#define PS_OFF (VS_OFF + 2 * FBUF_B)
#define FL_SMEM (PS_OFF + FBUF_B)     // 208,896 B

__device__ __forceinline__ void fl_load_tile_td(
    const __half* __restrict__ src, uint32_t dst, size_t row_stride, int row0, int tid)
{
    #pragma unroll
    for (int it = 0; it < 8; it++) {
        int idx = it * 256 + tid;
        int r = idx >> 4, c = idx & 15;
        cp_async16(dst + (uint32_t)(r * FROW_B + c * 16),
                   src + (size_t)(row0 + r) * row_stride + c * 8);
    }
}

__device__ __forceinline__ void fl_load_v(
    const __half* __restrict__ Vh, uint32_t dst, int kbase, int tid)
{
    #pragma unroll
    for (int it = 0; it < 8; it++) {
        int idx = it * 256 + tid;
        int r = idx >> 4, c = idx & 15;
        cp_async16(dst + (uint32_t)(r * FROW_B + c * 16),
                   Vh + (size_t)r * T_SEQ + kbase + c * 8);
    }
}

__global__ __launch_bounds__(256, 1)
void flash_mma(const __half* __restrict__ Qg, const __half* __restrict__ Kg,
               const __half* __restrict__ Vg, __half* __restrict__ Ctx)
{
    extern __shared__ __align__(16) char smc[];
    __half* Ps = (__half*)(smc + PS_OFF);

    const int tid  = threadIdx.x;
    const int w    = tid >> 5;
    const int lane = tid & 31;
    const int g    = lane >> 2;
    const int qd   = lane & 3;
    const int qt   = gridDim.x - 1 - blockIdx.x;
    const int h    = blockIdx.y;
    const int kh   = h >> 2;
    const int qbase = qt * 128;
    const int r0   = 16 * w + g;

    const __half* Qh = Qg + (size_t)h * T_SEQ * DH;
    const __half* Kh = Kg + (size_t)kh * T_SEQ * DH;
    const __half* Vh = Vg + (size_t)kh * DH * T_SEQ;

    const uint32_t smu = smem_to_u32(smc);
    const uint32_t qsu = smu + QS_OFF;
    const uint32_t ksu = smu + KS_OFF;
    const uint32_t vsu = smu + VS_OFF;
    const uint32_t psu = smu + PS_OFF;

    const uint32_t aSel = ((lane >> 3) & 1);
    const uint32_t aCol = ((lane >> 4) & 1);
    const uint32_t bSel = ((lane >> 4) & 1);
    const uint32_t bCol = ((lane >> 3) & 1);
    const int      lr   = lane & 7;

    const uint32_t qOffL = (uint32_t)(16 * w + aSel * 8 + lr) * FROW_B + aCol * 16;
    const uint32_t kOffL = (uint32_t)(bSel * 8 + lr) * FROW_B + bCol * 16;
    const uint32_t vOffL = (uint32_t)(bSel * 8 + lr) * FROW_B + bCol * 16;
    const uint32_t pOffL = (uint32_t)(16 * w + aSel * 8 + lr) * FROW_B + aCol * 16;

    const int ntiles = qt + 1;

    fl_load_tile_td(Qh, qsu, DH, qbase, tid);
    fl_load_tile_td(Kh, ksu, DH, 0, tid);
    fl_load_v(Vh, vsu, 0, tid);
    CP_COMMIT();

    float m_i[2] = {-1e30f, -1e30f};
    float l_i[2] = {0.f, 0.f};
    float o[16][4];
    #pragma unroll
    for (int nt = 0; nt < 16; nt++)
        #pragma unroll
        for (int e = 0; e < 4; e++) o[nt][e] = 0.f;

    for (int jt = 0; jt < ntiles; jt++) {
        CP_WAIT_0();
        __syncthreads();

        if (jt + 1 < ntiles) {
            uint32_t kdst = ksu + ((jt + 1) & 1) * FBUF_B;
            uint32_t vdst = vsu + ((jt + 1) & 1) * FBUF_B;
            fl_load_tile_td(Kh, kdst, DH, (jt + 1) * 128, tid);
            fl_load_v(Vh, vdst, (jt + 1) * 128, tid);
            CP_COMMIT();
        }

        const int kbase = jt * 128;
        const uint32_t kb = ksu + (jt & 1) * FBUF_B + kOffL;
        const uint32_t vb = vsu + (jt & 1) * FBUF_B + vOffL;

        float s[16][4];
        #pragma unroll
        for (int nt = 0; nt < 16; nt++)
            #pragma unroll
            for (int e = 0; e < 4; e++) s[nt][e] = 0.f;

        #pragma unroll
        for (int kk = 0; kk < 8; kk++) {
            uint32_t qf[4];
            ldsm_x4(qf[0], qf[1], qf[2], qf[3], qsu + qOffL + kk * 32);
            #pragma unroll
            for (int ntp = 0; ntp < 8; ntp++) {
                uint32_t b0, b1, b2, b3;
                ldsm_x4(b0, b1, b2, b3,
                        kb + (uint32_t)(ntp * 16 * FROW_B) + kk * 32);
                uint32_t bb0[2] = {b0, b1};
                uint32_t bb1[2] = {b2, b3};
                mma_f16(s[2*ntp],     qf, bb0);
                mma_f16(s[2*ntp + 1], qf, bb1);
            }
        }

        if (jt == qt) {
            #pragma unroll
            for (int nt = 0; nt < 16; nt++)
                #pragma unroll
                for (int e = 0; e < 4; e++) {
                    int col = kbase + nt * 8 + 2 * qd + (e & 1);
                    int row = qbase + r0 + ((e >> 1) << 3);
                    if (col > row) s[nt][e] = -1e30f;
                }
        }

        float mx0 = -1e30f, mx1 = -1e30f;
        #pragma unroll
        for (int nt = 0; nt < 16; nt++) {
            mx0 = fmaxf(mx0, fmaxf(s[nt][0], s[nt][1]));
            mx1 = fmaxf(mx1, fmaxf(s[nt][2], s[nt][3]));
        }
        mx0 = fmaxf(mx0, __shfl_xor_sync(0xffffffffu, mx0, 1));
        mx0 = fmaxf(mx0, __shfl_xor_sync(0xffffffffu, mx0, 2));
        mx1 = fmaxf(mx1, __shfl_xor_sync(0xffffffffu, mx1, 1));
        mx1 = fmaxf(mx1, __shfl_xor_sync(0xffffffffu, mx1, 2));
        float mn0 = fmaxf(m_i[0], mx0);
        float mn1 = fmaxf(m_i[1], mx1);
        float sc0 = exp2f(m_i[0] - mn0);
        float sc1 = exp2f(m_i[1] - mn1);
        m_i[0] = mn0; m_i[1] = mn1;

        float rs0 = 0.f, rs1 = 0.f;
        #pragma unroll
        for (int nt = 0; nt < 16; nt++) {
            s[nt][0] = exp2f(s[nt][0] - mn0);
            s[nt][1] = exp2f(s[nt][1] - mn0);
            s[nt][2] = exp2f(s[nt][2] - mn1);
            s[nt][3] = exp2f(s[nt][3] - mn1);
            rs0 += s[nt][0] + s[nt][1];
            rs1 += s[nt][2] + s[nt][3];
        }
        rs0 += __shfl_xor_sync(0xffffffffu, rs0, 1);
        rs0 += __shfl_xor_sync(0xffffffffu, rs0, 2);
        rs1 += __shfl_xor_sync(0xffffffffu, rs1, 1);
        rs1 += __shfl_xor_sync(0xffffffffu, rs1, 2);
        l_i[0] = l_i[0] * sc0 + rs0;
        l_i[1] = l_i[1] * sc1 + rs1;

        #pragma unroll
        for (int nt = 0; nt < 16; nt++) {
            o[nt][0] *= sc0; o[nt][1] *= sc0;
            o[nt][2] *= sc1; o[nt][3] *= sc1;
        }
        #pragma unroll
        for (int nt = 0; nt < 16; nt++) {
            *(__half2*)&Ps[(r0    ) * (FROW_B/2) + nt * 8 + 2 * qd] =
                __floats2half2_rn(s[nt][0], s[nt][1]);
            *(__half2*)&Ps[(r0 + 8) * (FROW_B/2) + nt * 8 + 2 * qd] =
                __floats2half2_rn(s[nt][2], s[nt][3]);
        }
        __syncwarp();

        #pragma unroll
        for (int kk = 0; kk < 8; kk++) {
            uint32_t a[4];
            ldsm_x4(a[0], a[1], a[2], a[3], psu + pOffL + kk * 32);
            #pragma unroll
            for (int dg = 0; dg < 8; dg++) {
                uint32_t b0, b1, b2, b3;
                ldsm_x4(b0, b1, b2, b3,
                        vb + (uint32_t)(dg * 16 * FROW_B) + kk * 32);
                uint32_t bb0[2] = {b0, b1};
                uint32_t bb1[2] = {b2, b3};
                mma_f16(o[2*dg],     a, bb0);
                mma_f16(o[2*dg + 1], a, bb1);
            }
        }
    }

    float inv0 = 1.0f / l_i[0];
    float inv1 = 1.0f / l_i[1];
    #pragma unroll
    for (int nt = 0; nt < 16; nt++) {
        size_t b0 = (size_t)(qbase + r0    ) * D_MODEL + h * DH + nt * 8 + 2 * qd;
        size_t b1 = (size_t)(qbase + r0 + 8) * D_MODEL + h * DH + nt * 8 + 2 * qd;
        *(__half2*)&Ctx[b0] = __floats2half2_rn(o[nt][0] * inv0, o[nt][1] * inv0);
        *(__half2*)&Ctx[b1] = __floats2half2_rn(o[nt][2] * inv1, o[nt][3] * inv1);
    }
}

// ---------------------------------------------------------------------------
// kernel_launch
// ---------------------------------------------------------------------------
extern "C" void kernel_launch(void* const* d_in, const int* in_sizes, int n_in,
                              void* d_out, int out_size)
{
    const float* x  = (const float*)d_in[0];
    const float* WQ = (const float*)d_in[1];
    const float* WK = (const float*)d_in[2];
    const float* WV = (const float*)d_in[3];
    const float* WO = (const float*)d_in[4];
    float* out = (float*)d_out;

    __half *qp, *kp, *vp, *cp, *xh, *wqkv, *wot;
    cudaGetSymbolAddress((void**)&qp,   g_Q);
    cudaGetSymbolAddress((void**)&kp,   g_K);
    cudaGetSymbolAddress((void**)&vp,   g_V);
    cudaGetSymbolAddress((void**)&cp,   g_C);
    cudaGetSymbolAddress((void**)&xh,   g_Xh);
    cudaGetSymbolAddress((void**)&wqkv, g_Wqkv);
    cudaGetSymbolAddress((void**)&wot,  g_WOt);

    cudaFuncSetAttribute(flash_mma,
                         cudaFuncAttributeMaxDynamicSharedMemorySize, FL_SMEM);
    cudaFuncSetAttribute(gemm_mma,
                         cudaFuncAttributeMaxDynamicSharedMemorySize, GM_SMEM);

    // 1) round x to fp16 (+ fill omega table once)
    {
        int n4 = T_SEQ * D_MODEL / 4;
        round_fp16_kernel<<<(n4 + 255) / 256, 256>>>((const float4*)x, (__half2*)xh, n4);
    }
    // 2) all weight transposes (fp16) in one launch
    transpose_rnd4<<<dim3(64, 64, 4), dim3(32, 8)>>>(WQ, WK, WV, WO);

    // 3) fused QKV projection (fp16 MMA, K-tile 64; epilogue: RoPE via table)
    gemm_mma<<<dim3(NQKV/128, T_SEQ/128), 256, GM_SMEM>>>(xh, wqkv, nullptr,
                                                          T_SEQ, NQKV, D_MODEL, 3);

    // 4) attention (fp16 tensor cores, kv-tile 128, exp2 softmax)
    flash_mma<<<dim3(T_SEQ/128, NH), 256, FL_SMEM>>>(qp, kp, vp, cp);

    // 5) output projection (fp16 MMA, fp32 out)
    gemm_mma<<<dim3(D_MODEL/128, T_SEQ/128), 256, GM_SMEM>>>(cp, wot, out,
                                                             T_SEQ, D_MODEL, D_MODEL, 0);
}